// round 13
// baseline (speedup 1.0000x reference)
#include <cuda_runtime.h>
#include <cuda_pipeline.h>
#include <math.h>
#include <stdint.h>

// ---------------- problem constants ----------------
#define NB 32
#define NT 2048
#define NIN 36
#define NH 256          // HIDDEN
#define NCD 128         // CODE_DIM
#define NCODES 1024
#define NSTR 4
#define NK (NT / NSTR)  // 512
#define NG 8            // GN groups
#define NRES 4

typedef unsigned long long u64t;

// ---------------- scratch (static device globals; no allocation) ----------------
__device__ float g_bufA[NB * NH * NT];   // 64 MB
__device__ float g_bufB[NB * NH * NT];   // 64 MB
__device__ float g_bufC[NB * NH * NT];   // 64 MB (also reused as dot buffer)
__device__ float g_small[NB * NH * NK];  // 16 MB
__device__ float g_ze[NB * NCD * NK];    // 8 MB
__device__ float g_zq[NB * NCD * NK];    // 8 MB (straight-through z_q_st)
__device__ int   g_codes[NB * NK];
__device__ float g_mu[NB * NG];
__device__ float g_rs[NB * NG];
__device__ float g_cb2[NCODES];
__device__ float g_counts[NCODES];
__device__ float g_acc[4];               // 0: vq sumsq, 1: pos sum, 2: dir num, 3: dir den
__device__ float g_part[NB * NG * 16 * 2]; // fused GN partials: [(b*8+g)*16+tile]*2
// pre-transposed, pre-duplicated res-block weights:
#define WT_PER_LAYER (2 * 32 * 8 * 3 * 128)   // 196608 u64
__device__ u64t g_wT[16 * WT_PER_LAYER];      // 25 MB
// co-paired weights for down conv & up conv-transpose: [z][ci 0..255][kk 0..7][p 0..63]
#define WDU_ELEMS (2 * 256 * 8 * 64)          // 262144 u64 = 2 MB each
__device__ u64t g_wdown[WDU_ELEMS];
__device__ u64t g_wup[WDU_ELEMS];
// code-paired codebook for VQ dot: [c 0..127][p 0..511] = (cb[2p][c], cb[2p+1][c])
__device__ u64t g_wcb[NCD * (NCODES / 2)];    // 512 KB

// dynamic smem layout for conv3k (per buffer): s_in(4224) s_inB(4224) s_w2(24576)
#define C3_BUF 33024
#define C3_SMEM (2 * C3_BUF)

// ---------------- packed f32x2 helpers (sm_103a FFMA2) ----------------
__device__ __forceinline__ u64t pk2(float lo, float hi) {
    u64t r; asm("mov.b64 %0, {%1, %2};" : "=l"(r) : "f"(lo), "f"(hi)); return r;
}
__device__ __forceinline__ u64t fma2(u64t a, u64t b, u64t c) {
    u64t d; asm("fma.rn.f32x2 %0, %1, %2, %3;" : "=l"(d) : "l"(a), "l"(b), "l"(c)); return d;
}
__device__ __forceinline__ void upk2(u64t p, float& lo, float& hi) {
    asm("mov.b64 {%0, %1}, %2;" : "=f"(lo), "=f"(hi) : "l"(p));
}

// ---------------- helpers ----------------
__device__ __forceinline__ float blockReduceSum256(float v) {
    __shared__ float sh[8];
    __syncthreads();
    #pragma unroll
    for (int o = 16; o; o >>= 1) v += __shfl_down_sync(0xffffffffu, v, o);
    if ((threadIdx.x & 31) == 0) sh[threadIdx.x >> 5] = v;
    __syncthreads();
    float s = 0.f;
    if (threadIdx.x == 0) {
        #pragma unroll
        for (int i = 0; i < 8; i++) s += sh[i];
    }
    return s;  // valid on thread 0 only
}

__device__ __forceinline__ float silu(float y) {
    return y * (1.0f / (1.0f + expf(-y)));
}

// ---------------- weight pre-transpose: res-block convs (dup-u64) ----------------
__global__ __launch_bounds__(256)
void wprep_k(const float* __restrict__ c1e, const float* __restrict__ c2e,
             const float* __restrict__ c1d, const float* __restrict__ c2d,
             u64t* __restrict__ wT)
{
    size_t i = (size_t)blockIdx.x * 256 + threadIdx.x;
    int l    = (int)(i / WT_PER_LAYER);
    int rem  = (int)(i % WT_PER_LAYER);
    int co   = rem & 127;
    int rem2 = rem >> 7;
    int kk   = rem2 % 3;
    int rem3 = rem2 / 3;
    int ci   = rem3 & 7;
    int blk  = rem3 >> 3;
    int c0   = blk & 31;
    int cb   = blk >> 5;
    const float* base = (l < 4) ? c1e : (l < 8) ? c2e : (l < 12) ? c1d : c2d;
    const float* wl = base + (size_t)(l & 3) * (256 * 256 * 3);
    float v = wl[((size_t)(cb * 128 + co) * 256 + c0 * 8 + ci) * 3 + kk];
    ((float2*)wT)[i] = make_float2(v, v);
}

// ---------------- weight pre-pack: down conv, co-pairs ----------------
__global__ __launch_bounds__(256)
void wprep_down(const float* __restrict__ dw, u64t* __restrict__ w2)
{
    int i = blockIdx.x * 256 + threadIdx.x;
    int p  = i & 63;
    int kk = (i >> 6) & 7;
    int ci = (i >> 9) & 255;
    int z  = i >> 17;
    int co = z * 128 + 2 * p;
    float a = dw[((size_t)co * 256 + ci) * 8 + kk];
    float b = dw[((size_t)(co + 1) * 256 + ci) * 8 + kk];
    ((float2*)w2)[i] = make_float2(a, b);
}

// ---------------- weight pre-pack: up conv-transpose, co-pairs ----------------
__global__ __launch_bounds__(256)
void wprep_up(const float* __restrict__ uw, u64t* __restrict__ w2)
{
    int i = blockIdx.x * 256 + threadIdx.x;
    int p  = i & 63;
    int kk = (i >> 6) & 7;
    int ci = (i >> 9) & 255;
    int z  = i >> 17;
    int co = z * 128 + 2 * p;
    float a = uw[((size_t)ci * 256 + co) * 8 + kk];
    float b = uw[((size_t)ci * 256 + co + 1) * 8 + kk];
    ((float2*)w2)[i] = make_float2(a, b);
}

// ---------------- codebook pre-pack: code-pairs, [c][p] layout ----------------
__global__ __launch_bounds__(256)
void cbprep_k(const float* __restrict__ cb, u64t* __restrict__ w2)
{
    int i = blockIdx.x * 256 + threadIdx.x;   // < 128*512
    int p = i & 511;
    int c = i >> 9;
    float a = cb[(size_t)(2 * p) * NCD + c];
    float b = cb[(size_t)(2 * p + 1) * NCD + c];
    ((float2*)w2)[(size_t)c * 512 + p] = make_float2(a, b);
}

// ---------------- specialized k=3 s=1 p=1 conv (R8 config) + fused GN partial stats ----------------
template<bool GN, bool RES, bool STATS>
__global__ __launch_bounds__(256)
void conv3k(const float* __restrict__ in, const u64t* __restrict__ wlayer,
            const float* __restrict__ bias, float* __restrict__ out,
            const float* __restrict__ resid,
            const float* __restrict__ gmu, const float* __restrict__ grs,
            const float* __restrict__ gga, const float* __restrict__ gbe,
            float* __restrict__ part)
{
    extern __shared__ char smraw[];
    __shared__ float sg[4][2];

    const int b   = blockIdx.y;
    const int ot0 = blockIdx.x * 128;
    const int tid = threadIdx.x;
    const int tx  = tid & 15;
    const int ty  = tid >> 4;

    const u64t* wtile_base = wlayer + (size_t)blockIdx.z * (32 * 3072);
    const float* inb = in + (size_t)b * 256 * 2048;
    const int fci = tid >> 5;
    const int ftt = tid & 31;

    u64t acc[8][4];
    #pragma unroll
    for (int i = 0; i < 8; i++)
        #pragma unroll
        for (int j = 0; j < 4; j++) acc[i][j] = 0ull;

    float pv[5];

    auto issue_in = [&](int it) {
        int gci = it * 8 + fci;
        const float* ip = inb + (size_t)gci * 2048 + ot0 - 1;
        #pragma unroll
        for (int j = 0; j < 5; j++) {
            int t = ftt + 32 * j;
            int gt = ot0 - 1 + t;
            bool ok = (j < 4 || t < 130) && (gt >= 0) && (gt < 2048);
            pv[j] = ok ? ip[t] : 0.f;
        }
    };

    auto issue_w = [&](int it, int bufsel) {
        char* dst = smraw + bufsel * C3_BUF + 8448;
        const char* src = (const char*)(wtile_base + (size_t)it * 3072);
        #pragma unroll
        for (int c = 0; c < 6; c++)
            __pipeline_memcpy_async(dst + (c * 256 + tid) * 16,
                                    src + (c * 256 + tid) * 16, 16);
        __pipeline_commit();
    };

    auto store_in = [&](int it, int bufsel) {
        float* s_in  = (float*)(smraw + bufsel * C3_BUF);
        float* s_inB = s_in + 1056;
        int gci = it * 8 + fci;
        float m_ = 0.f, r_ = 0.f, ga_ = 0.f, be_ = 0.f;
        if (GN) {
            int gg = gci >> 5;
            m_ = gmu[b * NG + gg];
            r_ = grs[b * NG + gg];
            ga_ = gga[gci];
            be_ = gbe[gci];
        }
        #pragma unroll
        for (int j = 0; j < 5; j++) {
            int t = ftt + 32 * j;
            if (j < 4 || t < 130) {
                int gt = ot0 - 1 + t;
                float v = 0.f;
                if (gt >= 0 && gt < 2048) {
                    v = pv[j];
                    if (GN) {
                        float y = (v - m_) * r_ * ga_ + be_;
                        v = silu(y);
                    }
                }
                s_in[fci * 132 + t] = v;
                if (t >= 1) s_inB[fci * 132 + t - 1] = v;
            }
        }
    };

    if (STATS && tid < 4) { sg[tid][0] = 0.f; sg[tid][1] = 0.f; }

    issue_in(0);
    issue_w(0, 0);
    store_in(0, 0);
    __pipeline_wait_prior(0);
    __syncthreads();

    for (int it = 0; it < 32; it++) {
        const int cur = it & 1;
        if (it < 31) {
            issue_in(it + 1);
            issue_w(it + 1, cur ^ 1);
        }
        const float* s_in  = (const float*)(smraw + cur * C3_BUF);
        const float* s_inB = s_in + 1056;
        const u64t*  s_w2  = (const u64t*)(smraw + cur * C3_BUF + 8448);
        #pragma unroll
        for (int ci = 0; ci < 8; ci++) {
            u64t P[2][3], Q[2][2];
            #pragma unroll
            for (int g = 0; g < 2; g++) {
                int t0 = tx * 4 + 64 * g;
                P[g][0] = *(const u64t*)&s_in[ci * 132 + t0];
                P[g][1] = *(const u64t*)&s_in[ci * 132 + t0 + 2];
                P[g][2] = *(const u64t*)&s_in[ci * 132 + t0 + 4];
                Q[g][0] = *(const u64t*)&s_inB[ci * 132 + t0];
                Q[g][1] = *(const u64t*)&s_inB[ci * 132 + t0 + 2];
            }
            #pragma unroll
            for (int kk = 0; kk < 3; kk++) {
                u64t wv[8];
                #pragma unroll
                for (int i = 0; i < 8; i++) {
                    int co = ty * 4 + (i & 3) + ((i >> 2) << 6);
                    wv[i] = s_w2[ci * 384 + kk * 128 + co];
                }
                #pragma unroll
                for (int i = 0; i < 8; i++) {
                    #pragma unroll
                    for (int g = 0; g < 2; g++) {
                        u64t x0, x1;
                        if (kk == 0)      { x0 = P[g][0]; x1 = P[g][1]; }
                        else if (kk == 1) { x0 = Q[g][0]; x1 = Q[g][1]; }
                        else              { x0 = P[g][1]; x1 = P[g][2]; }
                        acc[i][g * 2 + 0] = fma2(wv[i], x0, acc[i][g * 2 + 0]);
                        acc[i][g * 2 + 1] = fma2(wv[i], x1, acc[i][g * 2 + 1]);
                    }
                }
            }
        }
        if (it < 31) {
            store_in(it + 1, cur ^ 1);
            __pipeline_wait_prior(0);
        }
        __syncthreads();
    }

    const int co0 = blockIdx.z * 128;
    float sA1 = 0.f, sA2 = 0.f, sB1 = 0.f, sB2 = 0.f;
    #pragma unroll
    for (int i = 0; i < 8; i++) {
        int co = co0 + ty * 4 + (i & 3) + ((i >> 2) << 6);
        float bv = bias[co];
        float* op = out + ((size_t)b * 256 + co) * 2048;
        const float* rp = RES ? (resid + ((size_t)b * 256 + co) * 2048) : nullptr;
        #pragma unroll
        for (int g = 0; g < 2; g++) {
            int t0 = ot0 + tx * 4 + 64 * g;
            float e0, e1, e2, e3;
            upk2(acc[i][g * 2 + 0], e0, e1);
            upk2(acc[i][g * 2 + 1], e2, e3);
            e0 = __fadd_rn(e0, bv);
            e1 = __fadd_rn(e1, bv);
            e2 = __fadd_rn(e2, bv);
            e3 = __fadd_rn(e3, bv);
            if (RES) {
                float4 rv = *(const float4*)(rp + t0);
                e0 = __fadd_rn(rv.x, e0);
                e1 = __fadd_rn(rv.y, e1);
                e2 = __fadd_rn(rv.z, e2);
                e3 = __fadd_rn(rv.w, e3);
            }
            if (STATS) {
                float ss = (e0 + e1) + (e2 + e3);
                float sq = (e0 * e0 + e1 * e1) + (e2 * e2 + e3 * e3);
                if (i < 4) { sA1 += ss; sA2 += sq; }
                else       { sB1 += ss; sB2 += sq; }
            }
            float4 ov; ov.x = e0; ov.y = e1; ov.z = e2; ov.w = e3;
            *(float4*)(op + t0) = ov;
        }
    }
    if (STATS) {
        int lg = ty >> 3;   // local group within half: 0/1
        atomicAdd(&sg[lg][0], sA1);
        atomicAdd(&sg[lg][1], sA2);
        atomicAdd(&sg[2 + lg][0], sB1);
        atomicAdd(&sg[2 + lg][1], sB2);
        __syncthreads();
        if (tid < 4) {
            int gglob = blockIdx.z * 4 + tid;
            int slot = ((b * NG + gglob) * 16 + blockIdx.x) * 2;
            part[slot]     = sg[tid][0];
            part[slot + 1] = sg[tid][1];
        }
    }
}

// ---------------- GN finalize from fused partials: var = E[x^2] - mu^2 ----------------
__global__ void gnfin_k(const float* __restrict__ part,
                        float* __restrict__ mu, float* __restrict__ rs)
{
    int bg = blockIdx.x;     // < 256
    int lane = threadIdx.x;  // 32
    float s1 = 0.f, s2 = 0.f;
    if (lane < 16) {
        s1 = part[(bg * 16 + lane) * 2];
        s2 = part[(bg * 16 + lane) * 2 + 1];
    }
    #pragma unroll
    for (int o = 8; o; o >>= 1) {
        s1 += __shfl_down_sync(0xffffffffu, s1, o);
        s2 += __shfl_down_sync(0xffffffffu, s2, o);
    }
    if (lane == 0) {
        float m = s1 * (1.f / 65536.f);
        float var = fmaxf(s2 * (1.f / 65536.f) - m * m, 0.f);
        mu[bg] = m;
        rs[bg] = rsqrtf(var + 1e-5f);
    }
}

// ---------------- down conv (k=8,s=4,p=2), co-paired f32x2 ----------------
__global__ __launch_bounds__(256)
void down_k(const float* __restrict__ in, const u64t* __restrict__ w2,
            const float* __restrict__ bias, float* __restrict__ out)
{
    __shared__ u64t s_in2[4][264];
    __shared__ u64t s_w[4][8][64];

    const int b   = blockIdx.y;
    const int ot0 = blockIdx.x * 64;
    const int z   = blockIdx.z;
    const int tid = threadIdx.x;
    const int tx  = tid & 15;
    const int ty  = tid >> 4;

    const float* inb = in + (size_t)b * 256 * 2048;
    const u64t* wz = w2 + (size_t)z * (256 * 8 * 64);

    u64t acc[4][4];
    #pragma unroll
    for (int i = 0; i < 4; i++)
        #pragma unroll
        for (int j = 0; j < 4; j++) acc[i][j] = 0ull;

    for (int ci0 = 0; ci0 < 256; ci0 += 4) {
        __syncthreads();
        for (int idx = tid; idx < 4 * 260; idx += 256) {
            int ci = idx / 260, t = idx % 260;
            int gt = ot0 * 4 - 2 + t;
            float v = (gt >= 0 && gt < 2048) ? inb[(size_t)(ci0 + ci) * 2048 + gt] : 0.f;
            s_in2[ci][t] = pk2(v, v);
        }
        {
            const u64t* src = wz + (size_t)ci0 * 512;
            u64t* dst = &s_w[0][0][0];
            #pragma unroll
            for (int c = 0; c < 8; c++)
                dst[c * 256 + tid] = src[c * 256 + tid];
        }
        __syncthreads();
        #pragma unroll
        for (int ci = 0; ci < 4; ci++) {
            #pragma unroll
            for (int kk = 0; kk < 8; kk++) {
                u64t xr[4], wv[4];
                #pragma unroll
                for (int j = 0; j < 4; j++) xr[j] = s_in2[ci][(tx + 16 * j) * 4 + kk];
                #pragma unroll
                for (int i = 0; i < 4; i++) wv[i] = s_w[ci][kk][ty + 16 * i];
                #pragma unroll
                for (int i = 0; i < 4; i++)
                    #pragma unroll
                    for (int j = 0; j < 4; j++)
                        acc[i][j] = fma2(wv[i], xr[j], acc[i][j]);
            }
        }
    }
    #pragma unroll
    for (int i = 0; i < 4; i++) {
        int p = z * 64 + ty + 16 * i;
        int co0 = 2 * p, co1 = 2 * p + 1;
        float bv0 = bias[co0], bv1 = bias[co1];
        float* op0 = out + ((size_t)b * 256 + co0) * 512;
        float* op1 = out + ((size_t)b * 256 + co1) * 512;
        #pragma unroll
        for (int j = 0; j < 4; j++) {
            int t = ot0 + tx + 16 * j;
            float e0, e1;
            upk2(acc[i][j], e0, e1);
            op0[t] = __fadd_rn(e0, bv0);
            op1[t] = __fadd_rn(e1, bv1);
        }
    }
}

// ---------------- up conv-transpose (k=8,s=4,p=2), co-paired f32x2 ----------------
__global__ __launch_bounds__(256)
void up2_k(const float* __restrict__ in, const u64t* __restrict__ w2,
           const float* __restrict__ bias, float* __restrict__ out)
{
    constexpr int JT = 36;
    __shared__ u64t s_in2[8][40];
    __shared__ u64t s_w[8][8][64];

    const int b = blockIdx.y, ot0 = blockIdx.x * 128, z = blockIdx.z;
    const int tid = threadIdx.x, tx = tid & 15, ty = tid >> 4;
    const int j_lo = (ot0 == 0) ? -2 : ((ot0 - 5) >> 2);
    const int tbase = ot0 + tx;
    const int k0 = (tbase + 2) & 3;
    const int jjb = ((tbase + 2 - k0) >> 2) - j_lo;

    const u64t* wz = w2 + (size_t)z * (256 * 8 * 64);

    u64t acc[4][8];
    #pragma unroll
    for (int i = 0; i < 4; i++)
        #pragma unroll
        for (int j = 0; j < 8; j++) acc[i][j] = 0ull;

    for (int ci0 = 0; ci0 < 256; ci0 += 8) {
        __syncthreads();
        for (int idx = tid; idx < 8 * JT; idx += 256) {
            int ci = idx / JT, jj = idx % JT;
            int j = j_lo + jj;
            float v = (j >= 0 && j < NK) ? in[((size_t)b * 256 + ci0 + ci) * NK + j] : 0.f;
            s_in2[ci][jj] = pk2(v, v);
        }
        {
            const u64t* src = wz + (size_t)ci0 * 512;
            u64t* dst = &s_w[0][0][0];
            #pragma unroll
            for (int c = 0; c < 16; c++)
                dst[c * 256 + tid] = src[c * 256 + tid];
        }
        __syncthreads();
        #pragma unroll
        for (int ci = 0; ci < 8; ci++) {
            u64t w0[4], w1[4];
            #pragma unroll
            for (int i = 0; i < 4; i++) {
                w0[i] = s_w[ci][k0][ty + 16 * i];
                w1[i] = s_w[ci][k0 + 4][ty + 16 * i];
            }
            #pragma unroll
            for (int j = 0; j < 8; j++) {
                u64t i0 = s_in2[ci][jjb + 4 * j];
                u64t i1 = s_in2[ci][jjb + 4 * j - 1];
                #pragma unroll
                for (int i = 0; i < 4; i++) {
                    acc[i][j] = fma2(w0[i], i0, acc[i][j]);
                    acc[i][j] = fma2(w1[i], i1, acc[i][j]);
                }
            }
        }
    }
    #pragma unroll
    for (int i = 0; i < 4; i++) {
        int p = z * 64 + ty + 16 * i;
        int co0 = 2 * p, co1 = 2 * p + 1;
        float bv0 = bias[co0], bv1 = bias[co1];
        float* op0 = out + ((size_t)b * 256 + co0) * (size_t)NT;
        float* op1 = out + ((size_t)b * 256 + co1) * (size_t)NT;
        #pragma unroll
        for (int j = 0; j < 8; j++) {
            int t = ot0 + tx + 16 * j;
            float e0, e1;
            upk2(acc[i][j], e0, e1);
            op0[t] = __fadd_rn(e0, bv0);
            op1[t] = __fadd_rn(e1, bv1);
        }
    }
}

// ---------------- VQ dot GEMM: code-paired f32x2 ----------------
__global__ __launch_bounds__(256)
void vqdot2_k(const float* __restrict__ ze, const u64t* __restrict__ w2,
              float* __restrict__ dot)
{
    __shared__ u64t s_in2[16][64];
    __shared__ u64t s_w[16][128];

    const int b   = blockIdx.y;
    const int jt0 = blockIdx.x * 64;
    const int z   = blockIdx.z;
    const int tid = threadIdx.x;
    const int tx  = tid & 15;
    const int ty  = tid >> 4;

    u64t acc[8][4];
    #pragma unroll
    for (int i = 0; i < 8; i++)
        #pragma unroll
        for (int j = 0; j < 4; j++) acc[i][j] = 0ull;

    for (int ci0 = 0; ci0 < 128; ci0 += 16) {
        __syncthreads();
        for (int idx = tid; idx < 1024; idx += 256) {
            int ci = idx >> 6, t = idx & 63;
            float v = ze[((size_t)b * NCD + ci0 + ci) * NK + jt0 + t];
            s_in2[ci][t] = pk2(v, v);
        }
        for (int idx = tid; idx < 2048; idx += 256) {
            int ci = idx >> 7, p = idx & 127;
            s_w[ci][p] = w2[(size_t)(ci0 + ci) * 512 + z * 128 + p];
        }
        __syncthreads();
        #pragma unroll
        for (int ci = 0; ci < 16; ci++) {
            u64t xr[4], wv[8];
            #pragma unroll
            for (int j = 0; j < 4; j++) xr[j] = s_in2[ci][tx + 16 * j];
            #pragma unroll
            for (int i = 0; i < 8; i++) wv[i] = s_w[ci][ty + 16 * i];
            #pragma unroll
            for (int i = 0; i < 8; i++)
                #pragma unroll
                for (int j = 0; j < 4; j++)
                    acc[i][j] = fma2(wv[i], xr[j], acc[i][j]);
        }
    }
    #pragma unroll
    for (int i = 0; i < 8; i++) {
        int p = z * 128 + ty + 16 * i;
        float* o0 = dot + ((size_t)b * NCODES + 2 * p) * NK + jt0;
        float* o1 = dot + ((size_t)b * NCODES + 2 * p + 1) * NK + jt0;
        #pragma unroll
        for (int j = 0; j < 4; j++) {
            float e0, e1;
            upk2(acc[i][j], e0, e1);
            o0[tx + 16 * j] = e0;
            o1[tx + 16 * j] = e1;
        }
    }
}

// ---------------- generic direct conv ----------------
template<int KW, int STR, int PAD, int TTO, int COT, int TX, int RT, int RC, int CIC,
         bool INTR, bool OUTTR, bool GN>
__global__ __launch_bounds__(256)
void convk(const float* __restrict__ in, const float* __restrict__ w,
           const float* __restrict__ bias, float* __restrict__ out,
           const float* __restrict__ resid,
           const float* __restrict__ gmu, const float* __restrict__ grs,
           const float* __restrict__ gga, const float* __restrict__ gbe,
           int Cin, int Cout, int Tin, int Tout)
{
    constexpr int TY = 256 / TX;
    constexpr int IT = (TTO - 1) * STR + KW;
    static_assert(TX * RT == TTO, "t tiling");
    static_assert(TY * RC == COT, "c tiling");
    __shared__ float s_in[CIC][IT];
    __shared__ float s_w[CIC][KW][COT];

    const int b   = blockIdx.y;
    const int ot0 = blockIdx.x * TTO;
    const int co0 = blockIdx.z * COT;
    const int tid = threadIdx.x;
    const int tx  = tid % TX;
    const int ty  = tid / TX;

    float acc[RC][RT];
    #pragma unroll
    for (int i = 0; i < RC; i++)
        #pragma unroll
        for (int j = 0; j < RT; j++) acc[i][j] = 0.f;

    for (int ci0 = 0; ci0 < Cin; ci0 += CIC) {
        __syncthreads();
        for (int idx = tid; idx < CIC * IT; idx += 256) {
            int ci = idx / IT, t = idx % IT;
            int gci = ci0 + ci;
            int gt = ot0 * STR - PAD + t;
            float v = 0.f;
            if (gt >= 0 && gt < Tin) {
                v = INTR ? in[((size_t)b * Tin + gt) * Cin + gci]
                         : in[((size_t)b * Cin + gci) * (size_t)Tin + gt];
                if (GN) {
                    int gg = gci >> 5;
                    float y = (v - gmu[b * NG + gg]) * grs[b * NG + gg] * gga[gci] + gbe[gci];
                    v = silu(y);
                }
            }
            s_in[ci][t] = v;
        }
        for (int idx = tid; idx < CIC * KW * COT; idx += 256) {
            int ci = idx / (KW * COT);
            int r  = idx % (KW * COT);
            int kk = r / COT;
            int co = r % COT;
            s_w[ci][kk][co] = w[((size_t)(co0 + co) * Cin + ci0 + ci) * KW + kk];
        }
        __syncthreads();
        #pragma unroll 4
        for (int ci = 0; ci < CIC; ci++) {
            #pragma unroll
            for (int kk = 0; kk < KW; kk++) {
                float wr[RC], ir[RT];
                #pragma unroll
                for (int i = 0; i < RC; i++) wr[i] = s_w[ci][kk][ty + TY * i];
                #pragma unroll
                for (int j = 0; j < RT; j++) ir[j] = s_in[ci][(tx + TX * j) * STR + kk];
                #pragma unroll
                for (int i = 0; i < RC; i++)
                    #pragma unroll
                    for (int j = 0; j < RT; j++) acc[i][j] = fmaf(wr[i], ir[j], acc[i][j]);
            }
        }
    }
    #pragma unroll
    for (int i = 0; i < RC; i++) {
        int gco = co0 + ty + TY * i;
        float bv = bias ? bias[gco] : 0.f;
        #pragma unroll
        for (int j = 0; j < RT; j++) {
            int gt = ot0 + tx + TX * j;
            float v = __fadd_rn(acc[i][j], bv);
            if (resid) v = __fadd_rn(resid[((size_t)b * Cout + gco) * (size_t)Tout + gt], v);
            if (OUTTR) out[((size_t)b * Tout + gt) * Cout + gco] = v;
            else       out[((size_t)b * Cout + gco) * (size_t)Tout + gt] = v;
        }
    }
}

// ---------------- GroupNorm stats: two-pass, 512 threads (standalone, 2 uses) ----------------
__global__ __launch_bounds__(512)
void gnstats_k(const float* __restrict__ act, float* __restrict__ mu, float* __restrict__ rs)
{
    int bg = blockIdx.x;
    const float4* p = reinterpret_cast<const float4*>(act + (size_t)bg * 65536);
    __shared__ float sha[16];
    __shared__ float s_mu;

    float s = 0.f;
    for (int i = threadIdx.x; i < 16384; i += 512) {
        float4 v = p[i];
        s += v.x + v.y + v.z + v.w;
    }
    #pragma unroll
    for (int o = 16; o; o >>= 1) s += __shfl_down_sync(0xffffffffu, s, o);
    if ((threadIdx.x & 31) == 0) sha[threadIdx.x >> 5] = s;
    __syncthreads();
    if (threadIdx.x == 0) {
        float a = 0.f;
        #pragma unroll
        for (int i = 0; i < 16; i++) a += sha[i];
        s_mu = a * (1.f / 65536.f);
    }
    __syncthreads();
    float m = s_mu;

    float s2 = 0.f;
    for (int i = threadIdx.x; i < 16384; i += 512) {
        float4 v = p[i];
        float d0 = v.x - m, d1 = v.y - m, d2 = v.z - m, d3 = v.w - m;
        s2 += d0 * d0 + d1 * d1 + d2 * d2 + d3 * d3;
    }
    __syncthreads();
    #pragma unroll
    for (int o = 16; o; o >>= 1) s2 += __shfl_down_sync(0xffffffffu, s2, o);
    if ((threadIdx.x & 31) == 0) sha[threadIdx.x >> 5] = s2;
    __syncthreads();
    if (threadIdx.x == 0) {
        float c = 0.f;
        #pragma unroll
        for (int i = 0; i < 16; i++) c += sha[i];
        float var = c * (1.f / 65536.f);
        mu[bg] = m;
        rs[bg] = rsqrtf(var + 1e-5f);
    }
}

// ---------------- VQ helpers ----------------
__global__ void init_k(float* counts, float* acc)
{
    int i = blockIdx.x * 256 + threadIdx.x;
    if (i < NCODES) counts[i] = 0.f;
    if (i < 4) acc[i] = 0.f;
}

__global__ void cb2_k(const float* __restrict__ cb, float* __restrict__ cb2)
{
    int n = blockIdx.x * 256 + threadIdx.x;
    if (n < NCODES) {
        float s = 0.f;
        for (int c = 0; c < NCD; c++) {
            float v = cb[n * NCD + c];
            s = __fadd_rn(s, __fmul_rn(v, v));
        }
        cb2[n] = s;
    }
}

__global__ __launch_bounds__(256)
void argmin_k(const float* __restrict__ dot, const float* __restrict__ cb2,
              const float* __restrict__ ze,
              int* __restrict__ codes, float* __restrict__ counts, float* __restrict__ out_codes)
{
    int idx = blockIdx.x * 256 + threadIdx.x;
    int b = idx >> 9, j = idx & 511;
    const float* zp = ze + ((size_t)b * NCD) * NK + j;
    float z2 = 0.f;
    for (int c = 0; c < NCD; c++) {
        float v = zp[(size_t)c * NK];
        z2 = __fadd_rn(z2, __fmul_rn(v, v));
    }
    const float* dp = dot + ((size_t)b * NCODES) * NK + j;
    float best = 3.4e38f;
    int bn = 0;
    for (int n = 0; n < NCODES; n++) {
        float t = __fadd_rn(z2, cb2[n]);
        float v = __fsub_rn(t, __fmul_rn(2.f, dp[(size_t)n * NK]));
        if (v < best) { best = v; bn = n; }
    }
    codes[idx] = bn;
    atomicAdd(&counts[bn], 1.f);
    out_codes[idx] = (float)bn;
}

__global__ __launch_bounds__(256)
void zq_k(const float* __restrict__ ze, const float* __restrict__ cb,
          const int* __restrict__ codes, float* __restrict__ zq_st, float* __restrict__ acc)
{
    int i = blockIdx.x * 256 + threadIdx.x;
    int j = i & 511;
    int c = (i >> 9) & 127;
    int b = i >> 16;
    int code = codes[(b << 9) | j];
    float q = cb[code * NCD + c];
    float z = ze[i];
    float d = __fsub_rn(q, z);
    zq_st[i] = __fadd_rn(z, d);
    float v = blockReduceSum256(d * d);
    if (threadIdx.x == 0) atomicAdd(&acc[0], v);
}

// ---------------- recon losses ----------------
__global__ __launch_bounds__(256)
void recon_k(const float* __restrict__ x, const float* __restrict__ mask,
             const float* __restrict__ xhat, float* __restrict__ acc)
{
    int idx = blockIdx.x * 256 + threadIdx.x;
    const float* xr = x + (size_t)idx * NIN;
    const float* hr = xhat + (size_t)idx * NIN;
    float ps = 0.f;
    #pragma unroll
    for (int d = 0; d < 24; d++) {
        int dd = (d < 21) ? d : d + 6;
        float df = hr[dd] - xr[dd];
        float ad = fabsf(df);
        ps += (ad < 1.f) ? 0.5f * df * df : ad - 0.5f;
    }
    float mL = mask[(size_t)idx * 2 + 0];
    float mR = mask[(size_t)idx * 2 + 1];
    float dn = 0.f, dd_ = 0.f;
    const int off[4] = {21, 24, 30, 33};
    #pragma unroll
    for (int v = 0; v < 4; v++) {
        int o = off[v];
        float x0 = xr[o], x1 = xr[o + 1], x2 = xr[o + 2];
        float h0 = hr[o], h1 = hr[o + 1], h2 = hr[o + 2];
        float nx = sqrtf(x0 * x0 + x1 * x1 + x2 * x2) + 1e-8f;
        float nh = sqrtf(h0 * h0 + h1 * h1 + h2 * h2) + 1e-8f;
        float cs = (x0 * h0 + x1 * h1 + x2 * h2) / (nx * nh);
        float m = (v < 2) ? mL : mR;
        dn += (1.f - cs) * m;
        dd_ += m;
    }
    float r0 = blockReduceSum256(ps);
    float r1 = blockReduceSum256(dn);
    float r2 = blockReduceSum256(dd_);
    if (threadIdx.x == 0) {
        atomicAdd(&acc[1], r0);
        atomicAdd(&acc[2], r1);
        atomicAdd(&acc[3], r2);
    }
}

__global__ __launch_bounds__(1024)
void finalize_k(const float* __restrict__ counts, const float* __restrict__ acc,
                float* __restrict__ out)
{
    __shared__ float sh[32];
    int t = threadIdx.x;
    float a = counts[t] * (1.f / (float)(NB * NK));
    float v = a * logf(a + 1e-10f);
    #pragma unroll
    for (int o = 16; o; o >>= 1) v += __shfl_down_sync(0xffffffffu, v, o);
    if ((t & 31) == 0) sh[t >> 5] = v;
    __syncthreads();
    if (t == 0) {
        float s = 0.f;
        #pragma unroll
        for (int i = 0; i < 32; i++) s += sh[i];
        out[0] = acc[0] * (1.25f / (float)(NB * NCD * NK));
        out[1] = expf(-s);
        out[2] = acc[1] * (1.f / (float)(NB * NT));
        out[3] = acc[2] / fmaxf(acc[3], 1.f);
    }
}

// ---------------- host orchestration ----------------
extern "C" void kernel_launch(void* const* d_in, const int* in_sizes, int n_in,
                              void* d_out, int out_size)
{
    const float* x          = (const float*)d_in[0];
    const float* mask       = (const float*)d_in[1];
    const float* enc_in_w   = (const float*)d_in[2];
    const float* enc_in_b   = (const float*)d_in[3];
    const float* enc_gn1_g  = (const float*)d_in[4];
    const float* enc_gn1_b  = (const float*)d_in[5];
    const float* enc_c1_w   = (const float*)d_in[6];
    const float* enc_c1_b   = (const float*)d_in[7];
    const float* enc_gn2_g  = (const float*)d_in[8];
    const float* enc_gn2_b  = (const float*)d_in[9];
    const float* enc_c2_w   = (const float*)d_in[10];
    const float* enc_c2_b   = (const float*)d_in[11];
    const float* down_w     = (const float*)d_in[12];
    const float* down_b     = (const float*)d_in[13];
    const float* enc_out_w  = (const float*)d_in[14];
    const float* enc_out_b  = (const float*)d_in[15];
    const float* codebook   = (const float*)d_in[16];
    const float* dec_in_w   = (const float*)d_in[17];
    const float* dec_in_b   = (const float*)d_in[18];
    const float* up_w       = (const float*)d_in[19];
    const float* up_b       = (const float*)d_in[20];
    const float* dec_gn1_g  = (const float*)d_in[21];
    const float* dec_gn1_b  = (const float*)d_in[22];
    const float* dec_c1_w   = (const float*)d_in[23];
    const float* dec_c1_b   = (const float*)d_in[24];
    const float* dec_gn2_g  = (const float*)d_in[25];
    const float* dec_gn2_b  = (const float*)d_in[26];
    const float* dec_c2_w   = (const float*)d_in[27];
    const float* dec_c2_b   = (const float*)d_in[28];
    const float* dec_out_w  = (const float*)d_in[29];
    const float* dec_out_b  = (const float*)d_in[30];

    float *bufA, *bufB, *bufC, *small, *ze, *zq, *mu, *rs, *cb2, *counts, *acc, *part;
    int* codes;
    u64t *wT, *wdown, *wup, *wcb;
    cudaGetSymbolAddress((void**)&bufA, g_bufA);
    cudaGetSymbolAddress((void**)&bufB, g_bufB);
    cudaGetSymbolAddress((void**)&bufC, g_bufC);
    cudaGetSymbolAddress((void**)&small, g_small);
    cudaGetSymbolAddress((void**)&ze, g_ze);
    cudaGetSymbolAddress((void**)&zq, g_zq);
    cudaGetSymbolAddress((void**)&mu, g_mu);
    cudaGetSymbolAddress((void**)&rs, g_rs);
    cudaGetSymbolAddress((void**)&cb2, g_cb2);
    cudaGetSymbolAddress((void**)&counts, g_counts);
    cudaGetSymbolAddress((void**)&acc, g_acc);
    cudaGetSymbolAddress((void**)&part, g_part);
    cudaGetSymbolAddress((void**)&codes, g_codes);
    cudaGetSymbolAddress((void**)&wT, g_wT);
    cudaGetSymbolAddress((void**)&wdown, g_wdown);
    cudaGetSymbolAddress((void**)&wup, g_wup);
    cudaGetSymbolAddress((void**)&wcb, g_wcb);

    cudaFuncSetAttribute(conv3k<true, false, true>,
                         cudaFuncAttributeMaxDynamicSharedMemorySize, C3_SMEM);
    cudaFuncSetAttribute(conv3k<true, true, true>,
                         cudaFuncAttributeMaxDynamicSharedMemorySize, C3_SMEM);

    float* out = (float*)d_out;
    float* out_xhat = out;
    float* out_codes = out + (size_t)NB * NT * NIN;
    float* out_scal = out_codes + (size_t)NB * NK;

    init_k<<<4, 256>>>(counts, acc);
    wprep_k<<<(16 * WT_PER_LAYER) / 256, 256>>>(enc_c1_w, enc_c2_w, dec_c1_w, dec_c2_w, wT);
    wprep_down<<<WDU_ELEMS / 256, 256>>>(down_w, wdown);
    wprep_up<<<WDU_ELEMS / 256, 256>>>(up_w, wup);
    cbprep_k<<<(NCD * (NCODES / 2)) / 256, 256>>>(codebook, wcb);

    // ---- encoder ----
    convk<3, 1, 1, 128, 128, 16, 8, 8, 12, true, false, false><<<dim3(16, NB, 2), 256>>>(
        x, enc_in_w, enc_in_b, bufA, nullptr, nullptr, nullptr, nullptr, nullptr,
        NIN, NH, NT, NT);

    float* cur = bufA;
    float* oth = bufC;
    gnstats_k<<<NB * NG, 512>>>(cur, mu, rs);   // stats of enc_in output (standalone)
    for (int r = 0; r < NRES; r++) {
        conv3k<true, false, true><<<dim3(16, NB, 2), 256, C3_SMEM>>>(
            cur, wT + (size_t)r * WT_PER_LAYER, enc_c1_b + r * NH, bufB, nullptr,
            mu, rs, enc_gn1_g + r * NH, enc_gn1_b + r * NH, part);
        gnfin_k<<<NB * NG, 32>>>(part, mu, rs);
        conv3k<true, true, true><<<dim3(16, NB, 2), 256, C3_SMEM>>>(
            bufB, wT + (size_t)(4 + r) * WT_PER_LAYER, enc_c2_b + r * NH, oth, cur,
            mu, rs, enc_gn2_g + r * NH, enc_gn2_b + r * NH, part);
        if (r < NRES - 1) gnfin_k<<<NB * NG, 32>>>(part, mu, rs);
        float* t = cur; cur = oth; oth = t;
    }
    down_k<<<dim3(8, NB, 2), 256>>>(cur, wdown, down_b, small);
    convk<1, 1, 0, 128, 128, 16, 8, 8, 32, false, false, false><<<dim3(4, NB, 1), 256>>>(
        small, enc_out_w, enc_out_b, ze, nullptr, nullptr, nullptr, nullptr, nullptr,
        NH, NCD, NK, NK);

    // ---- VQ ----
    cb2_k<<<4, 256>>>(codebook, cb2);
    vqdot2_k<<<dim3(8, NB, 4), 256>>>(ze, wcb, bufC);
    argmin_k<<<(NB * NK) / 256, 256>>>(bufC, cb2, ze, codes, counts, out_codes);
    zq_k<<<(NB * NCD * NK) / 256, 256>>>(ze, codebook, codes, zq, acc);

    // ---- decoder ----
    convk<1, 1, 0, 128, 128, 16, 8, 8, 32, false, false, false><<<dim3(4, NB, 2), 256>>>(
        zq, dec_in_w, dec_in_b, small, nullptr, nullptr, nullptr, nullptr, nullptr,
        NCD, NH, NK, NK);
    up2_k<<<dim3(16, NB, 2), 256>>>(small, wup, up_b, bufA);

    cur = bufA;
    oth = bufC;
    gnstats_k<<<NB * NG, 512>>>(cur, mu, rs);   // stats of upconv output (standalone)
    for (int r = 0; r < NRES; r++) {
        conv3k<true, false, true><<<dim3(16, NB, 2), 256, C3_SMEM>>>(
            cur, wT + (size_t)(8 + r) * WT_PER_LAYER, dec_c1_b + r * NH, bufB, nullptr,
            mu, rs, dec_gn1_g + r * NH, dec_gn1_b + r * NH, part);
        gnfin_k<<<NB * NG, 32>>>(part, mu, rs);
        conv3k<true, true, true><<<dim3(16, NB, 2), 256, C3_SMEM>>>(
            bufB, wT + (size_t)(12 + r) * WT_PER_LAYER, dec_c2_b + r * NH, oth, cur,
            mu, rs, dec_gn2_g + r * NH, dec_gn2_b + r * NH, part);
        if (r < NRES - 1) gnfin_k<<<NB * NG, 32>>>(part, mu, rs);
        float* t = cur; cur = oth; oth = t;
    }
    convk<3, 1, 1, 128, 36, 64, 2, 9, 32, false, true, false><<<dim3(16, NB, 1), 256>>>(
        cur, dec_out_w, dec_out_b, out_xhat, nullptr, nullptr, nullptr, nullptr, nullptr,
        NH, NIN, NT, NT);

    // ---- losses ----
    recon_k<<<(NB * NT) / 256, 256>>>(x, mask, out_xhat, acc);
    finalize_k<<<1, 1024>>>(counts, acc, out_scal);
}

// round 14
// speedup vs baseline: 1.0997x; 1.0997x over previous
#include <cuda_runtime.h>
#include <cuda_pipeline.h>
#include <math.h>
#include <stdint.h>

// ---------------- problem constants ----------------
#define NB 32
#define NT 2048
#define NIN 36
#define NH 256          // HIDDEN
#define NCD 128         // CODE_DIM
#define NCODES 1024
#define NSTR 4
#define NK (NT / NSTR)  // 512
#define NG 8            // GN groups
#define NRES 4

typedef unsigned long long u64t;

// ---------------- scratch (static device globals; no allocation) ----------------
__device__ float g_bufA[NB * NH * NT];   // 64 MB
__device__ float g_bufB[NB * NH * NT];   // 64 MB
__device__ float g_bufC[NB * NH * NT];   // 64 MB (also reused as dot buffer)
__device__ float g_small[NB * NH * NK];  // 16 MB
__device__ float g_ze[NB * NCD * NK];    // 8 MB
__device__ float g_zq[NB * NCD * NK];    // 8 MB (straight-through z_q_st)
__device__ int   g_codes[NB * NK];
__device__ float g_mu[NB * NG];
__device__ float g_rs[NB * NG];
__device__ float g_cb2[NCODES];
__device__ float g_counts[NCODES];
__device__ float g_acc[4];               // 0: vq sumsq, 1: pos sum, 2: dir num, 3: dir den
// pre-transposed, pre-duplicated res-block weights:
#define WT_PER_LAYER (2 * 32 * 8 * 3 * 128)   // 196608 u64
__device__ u64t g_wT[16 * WT_PER_LAYER];      // 25 MB
// co-paired weights for down conv & up conv-transpose: [z][ci 0..255][kk 0..7][p 0..63]
#define WDU_ELEMS (2 * 256 * 8 * 64)          // 262144 u64 = 2 MB each
__device__ u64t g_wdown[WDU_ELEMS];
__device__ u64t g_wup[WDU_ELEMS];
// code-paired codebook for VQ dot: [c 0..127][p 0..511] = (cb[2p][c], cb[2p+1][c])
__device__ u64t g_wcb[NCD * (NCODES / 2)];    // 512 KB

// dynamic smem layout for conv3k (per buffer): s_in(4224) s_inB(4224) s_w2(24576)
#define C3_BUF 33024
#define C3_SMEM (2 * C3_BUF)

// ---------------- packed f32x2 helpers (sm_103a FFMA2) ----------------
__device__ __forceinline__ u64t pk2(float lo, float hi) {
    u64t r; asm("mov.b64 %0, {%1, %2};" : "=l"(r) : "f"(lo), "f"(hi)); return r;
}
__device__ __forceinline__ u64t fma2(u64t a, u64t b, u64t c) {
    u64t d; asm("fma.rn.f32x2 %0, %1, %2, %3;" : "=l"(d) : "l"(a), "l"(b), "l"(c)); return d;
}
__device__ __forceinline__ void upk2(u64t p, float& lo, float& hi) {
    asm("mov.b64 {%0, %1}, %2;" : "=f"(lo), "=f"(hi) : "l"(p));
}

// ---------------- helpers ----------------
__device__ __forceinline__ float blockReduceSum256(float v) {
    __shared__ float sh[8];
    __syncthreads();
    #pragma unroll
    for (int o = 16; o; o >>= 1) v += __shfl_down_sync(0xffffffffu, v, o);
    if ((threadIdx.x & 31) == 0) sh[threadIdx.x >> 5] = v;
    __syncthreads();
    float s = 0.f;
    if (threadIdx.x == 0) {
        #pragma unroll
        for (int i = 0; i < 8; i++) s += sh[i];
    }
    return s;  // valid on thread 0 only
}

__device__ __forceinline__ float silu(float y) {
    return y * (1.0f / (1.0f + expf(-y)));
}

// ---------------- weight pre-transpose: res-block convs (dup-u64) ----------------
__global__ __launch_bounds__(256)
void wprep_k(const float* __restrict__ c1e, const float* __restrict__ c2e,
             const float* __restrict__ c1d, const float* __restrict__ c2d,
             u64t* __restrict__ wT)
{
    size_t i = (size_t)blockIdx.x * 256 + threadIdx.x;
    int l    = (int)(i / WT_PER_LAYER);
    int rem  = (int)(i % WT_PER_LAYER);
    int co   = rem & 127;
    int rem2 = rem >> 7;
    int kk   = rem2 % 3;
    int rem3 = rem2 / 3;
    int ci   = rem3 & 7;
    int blk  = rem3 >> 3;
    int c0   = blk & 31;
    int cb   = blk >> 5;
    const float* base = (l < 4) ? c1e : (l < 8) ? c2e : (l < 12) ? c1d : c2d;
    const float* wl = base + (size_t)(l & 3) * (256 * 256 * 3);
    float v = wl[((size_t)(cb * 128 + co) * 256 + c0 * 8 + ci) * 3 + kk];
    ((float2*)wT)[i] = make_float2(v, v);
}

// ---------------- weight pre-pack: down conv, co-pairs ----------------
__global__ __launch_bounds__(256)
void wprep_down(const float* __restrict__ dw, u64t* __restrict__ w2)
{
    int i = blockIdx.x * 256 + threadIdx.x;
    int p  = i & 63;
    int kk = (i >> 6) & 7;
    int ci = (i >> 9) & 255;
    int z  = i >> 17;
    int co = z * 128 + 2 * p;
    float a = dw[((size_t)co * 256 + ci) * 8 + kk];
    float b = dw[((size_t)(co + 1) * 256 + ci) * 8 + kk];
    ((float2*)w2)[i] = make_float2(a, b);
}

// ---------------- weight pre-pack: up conv-transpose, co-pairs ----------------
__global__ __launch_bounds__(256)
void wprep_up(const float* __restrict__ uw, u64t* __restrict__ w2)
{
    int i = blockIdx.x * 256 + threadIdx.x;
    int p  = i & 63;
    int kk = (i >> 6) & 7;
    int ci = (i >> 9) & 255;
    int z  = i >> 17;
    int co = z * 128 + 2 * p;
    float a = uw[((size_t)ci * 256 + co) * 8 + kk];
    float b = uw[((size_t)ci * 256 + co + 1) * 8 + kk];
    ((float2*)w2)[i] = make_float2(a, b);
}

// ---------------- codebook pre-pack: code-pairs, [c][p] layout ----------------
__global__ __launch_bounds__(256)
void cbprep_k(const float* __restrict__ cb, u64t* __restrict__ w2)
{
    int i = blockIdx.x * 256 + threadIdx.x;   // < 128*512
    int p = i & 511;
    int c = i >> 9;
    float a = cb[(size_t)(2 * p) * NCD + c];
    float b = cb[(size_t)(2 * p + 1) * NCD + c];
    ((float2*)w2)[(size_t)c * 512 + p] = make_float2(a, b);
}

// ---------------- specialized k=3 s=1 p=1 conv (R8/R12 config, frozen) ----------------
template<bool GN, bool RES>
__global__ __launch_bounds__(256)
void conv3k(const float* __restrict__ in, const u64t* __restrict__ wlayer,
            const float* __restrict__ bias, float* __restrict__ out,
            const float* __restrict__ resid,
            const float* __restrict__ gmu, const float* __restrict__ grs,
            const float* __restrict__ gga, const float* __restrict__ gbe)
{
    extern __shared__ char smraw[];

    const int b   = blockIdx.y;
    const int ot0 = blockIdx.x * 128;
    const int tid = threadIdx.x;
    const int tx  = tid & 15;
    const int ty  = tid >> 4;

    const u64t* wtile_base = wlayer + (size_t)blockIdx.z * (32 * 3072);
    const float* inb = in + (size_t)b * 256 * 2048;
    const int fci = tid >> 5;
    const int ftt = tid & 31;

    u64t acc[8][4];
    #pragma unroll
    for (int i = 0; i < 8; i++)
        #pragma unroll
        for (int j = 0; j < 4; j++) acc[i][j] = 0ull;

    float pv[5];

    auto issue_in = [&](int it) {
        int gci = it * 8 + fci;
        const float* ip = inb + (size_t)gci * 2048 + ot0 - 1;
        #pragma unroll
        for (int j = 0; j < 5; j++) {
            int t = ftt + 32 * j;
            int gt = ot0 - 1 + t;
            bool ok = (j < 4 || t < 130) && (gt >= 0) && (gt < 2048);
            pv[j] = ok ? ip[t] : 0.f;
        }
    };

    auto issue_w = [&](int it, int bufsel) {
        char* dst = smraw + bufsel * C3_BUF + 8448;
        const char* src = (const char*)(wtile_base + (size_t)it * 3072);
        #pragma unroll
        for (int c = 0; c < 6; c++)
            __pipeline_memcpy_async(dst + (c * 256 + tid) * 16,
                                    src + (c * 256 + tid) * 16, 16);
        __pipeline_commit();
    };

    auto store_in = [&](int it, int bufsel) {
        float* s_in  = (float*)(smraw + bufsel * C3_BUF);
        float* s_inB = s_in + 1056;
        int gci = it * 8 + fci;
        float m_ = 0.f, r_ = 0.f, ga_ = 0.f, be_ = 0.f;
        if (GN) {
            int gg = gci >> 5;
            m_ = gmu[b * NG + gg];
            r_ = grs[b * NG + gg];
            ga_ = gga[gci];
            be_ = gbe[gci];
        }
        #pragma unroll
        for (int j = 0; j < 5; j++) {
            int t = ftt + 32 * j;
            if (j < 4 || t < 130) {
                int gt = ot0 - 1 + t;
                float v = 0.f;
                if (gt >= 0 && gt < 2048) {
                    v = pv[j];
                    if (GN) {
                        float y = (v - m_) * r_ * ga_ + be_;
                        v = silu(y);
                    }
                }
                s_in[fci * 132 + t] = v;
                if (t >= 1) s_inB[fci * 132 + t - 1] = v;
            }
        }
    };

    issue_in(0);
    issue_w(0, 0);
    store_in(0, 0);
    __pipeline_wait_prior(0);
    __syncthreads();

    for (int it = 0; it < 32; it++) {
        const int cur = it & 1;
        if (it < 31) {
            issue_in(it + 1);
            issue_w(it + 1, cur ^ 1);
        }
        const float* s_in  = (const float*)(smraw + cur * C3_BUF);
        const float* s_inB = s_in + 1056;
        const u64t*  s_w2  = (const u64t*)(smraw + cur * C3_BUF + 8448);
        #pragma unroll
        for (int ci = 0; ci < 8; ci++) {
            u64t P[2][3], Q[2][2];
            #pragma unroll
            for (int g = 0; g < 2; g++) {
                int t0 = tx * 4 + 64 * g;
                P[g][0] = *(const u64t*)&s_in[ci * 132 + t0];
                P[g][1] = *(const u64t*)&s_in[ci * 132 + t0 + 2];
                P[g][2] = *(const u64t*)&s_in[ci * 132 + t0 + 4];
                Q[g][0] = *(const u64t*)&s_inB[ci * 132 + t0];
                Q[g][1] = *(const u64t*)&s_inB[ci * 132 + t0 + 2];
            }
            #pragma unroll
            for (int kk = 0; kk < 3; kk++) {
                u64t wv[8];
                #pragma unroll
                for (int i = 0; i < 8; i++) {
                    int co = ty * 4 + (i & 3) + ((i >> 2) << 6);
                    wv[i] = s_w2[ci * 384 + kk * 128 + co];
                }
                #pragma unroll
                for (int i = 0; i < 8; i++) {
                    #pragma unroll
                    for (int g = 0; g < 2; g++) {
                        u64t x0, x1;
                        if (kk == 0)      { x0 = P[g][0]; x1 = P[g][1]; }
                        else if (kk == 1) { x0 = Q[g][0]; x1 = Q[g][1]; }
                        else              { x0 = P[g][1]; x1 = P[g][2]; }
                        acc[i][g * 2 + 0] = fma2(wv[i], x0, acc[i][g * 2 + 0]);
                        acc[i][g * 2 + 1] = fma2(wv[i], x1, acc[i][g * 2 + 1]);
                    }
                }
            }
        }
        if (it < 31) {
            store_in(it + 1, cur ^ 1);
            __pipeline_wait_prior(0);
        }
        __syncthreads();
    }

    const int co0 = blockIdx.z * 128;
    #pragma unroll
    for (int i = 0; i < 8; i++) {
        int co = co0 + ty * 4 + (i & 3) + ((i >> 2) << 6);
        float bv = bias[co];
        float* op = out + ((size_t)b * 256 + co) * 2048;
        const float* rp = RES ? (resid + ((size_t)b * 256 + co) * 2048) : nullptr;
        #pragma unroll
        for (int g = 0; g < 2; g++) {
            int t0 = ot0 + tx * 4 + 64 * g;
            float e0, e1, e2, e3;
            upk2(acc[i][g * 2 + 0], e0, e1);
            upk2(acc[i][g * 2 + 1], e2, e3);
            e0 = __fadd_rn(e0, bv);
            e1 = __fadd_rn(e1, bv);
            e2 = __fadd_rn(e2, bv);
            e3 = __fadd_rn(e3, bv);
            if (RES) {
                float4 rv = *(const float4*)(rp + t0);
                e0 = __fadd_rn(rv.x, e0);
                e1 = __fadd_rn(rv.y, e1);
                e2 = __fadd_rn(rv.z, e2);
                e3 = __fadd_rn(rv.w, e3);
            }
            float4 ov; ov.x = e0; ov.y = e1; ov.z = e2; ov.w = e3;
            *(float4*)(op + t0) = ov;
        }
    }
}

// ---------------- down conv (k=8,s=4,p=2), co-paired f32x2 ----------------
__global__ __launch_bounds__(256)
void down_k(const float* __restrict__ in, const u64t* __restrict__ w2,
            const float* __restrict__ bias, float* __restrict__ out)
{
    __shared__ u64t s_in2[4][264];
    __shared__ u64t s_w[4][8][64];

    const int b   = blockIdx.y;
    const int ot0 = blockIdx.x * 64;
    const int z   = blockIdx.z;
    const int tid = threadIdx.x;
    const int tx  = tid & 15;
    const int ty  = tid >> 4;

    const float* inb = in + (size_t)b * 256 * 2048;
    const u64t* wz = w2 + (size_t)z * (256 * 8 * 64);

    u64t acc[4][4];
    #pragma unroll
    for (int i = 0; i < 4; i++)
        #pragma unroll
        for (int j = 0; j < 4; j++) acc[i][j] = 0ull;

    for (int ci0 = 0; ci0 < 256; ci0 += 4) {
        __syncthreads();
        for (int idx = tid; idx < 4 * 260; idx += 256) {
            int ci = idx / 260, t = idx % 260;
            int gt = ot0 * 4 - 2 + t;
            float v = (gt >= 0 && gt < 2048) ? inb[(size_t)(ci0 + ci) * 2048 + gt] : 0.f;
            s_in2[ci][t] = pk2(v, v);
        }
        {
            const u64t* src = wz + (size_t)ci0 * 512;
            u64t* dst = &s_w[0][0][0];
            #pragma unroll
            for (int c = 0; c < 8; c++)
                dst[c * 256 + tid] = src[c * 256 + tid];
        }
        __syncthreads();
        #pragma unroll
        for (int ci = 0; ci < 4; ci++) {
            #pragma unroll
            for (int kk = 0; kk < 8; kk++) {
                u64t xr[4], wv[4];
                #pragma unroll
                for (int j = 0; j < 4; j++) xr[j] = s_in2[ci][(tx + 16 * j) * 4 + kk];
                #pragma unroll
                for (int i = 0; i < 4; i++) wv[i] = s_w[ci][kk][ty + 16 * i];
                #pragma unroll
                for (int i = 0; i < 4; i++)
                    #pragma unroll
                    for (int j = 0; j < 4; j++)
                        acc[i][j] = fma2(wv[i], xr[j], acc[i][j]);
            }
        }
    }
    #pragma unroll
    for (int i = 0; i < 4; i++) {
        int p = z * 64 + ty + 16 * i;
        int co0 = 2 * p, co1 = 2 * p + 1;
        float bv0 = bias[co0], bv1 = bias[co1];
        float* op0 = out + ((size_t)b * 256 + co0) * 512;
        float* op1 = out + ((size_t)b * 256 + co1) * 512;
        #pragma unroll
        for (int j = 0; j < 4; j++) {
            int t = ot0 + tx + 16 * j;
            float e0, e1;
            upk2(acc[i][j], e0, e1);
            op0[t] = __fadd_rn(e0, bv0);
            op1[t] = __fadd_rn(e1, bv1);
        }
    }
}

// ---------------- up conv-transpose (k=8,s=4,p=2), co-paired f32x2 ----------------
__global__ __launch_bounds__(256)
void up2_k(const float* __restrict__ in, const u64t* __restrict__ w2,
           const float* __restrict__ bias, float* __restrict__ out)
{
    constexpr int JT = 36;
    __shared__ u64t s_in2[8][40];
    __shared__ u64t s_w[8][8][64];

    const int b = blockIdx.y, ot0 = blockIdx.x * 128, z = blockIdx.z;
    const int tid = threadIdx.x, tx = tid & 15, ty = tid >> 4;
    const int j_lo = (ot0 == 0) ? -2 : ((ot0 - 5) >> 2);
    const int tbase = ot0 + tx;
    const int k0 = (tbase + 2) & 3;
    const int jjb = ((tbase + 2 - k0) >> 2) - j_lo;

    const u64t* wz = w2 + (size_t)z * (256 * 8 * 64);

    u64t acc[4][8];
    #pragma unroll
    for (int i = 0; i < 4; i++)
        #pragma unroll
        for (int j = 0; j < 8; j++) acc[i][j] = 0ull;

    for (int ci0 = 0; ci0 < 256; ci0 += 8) {
        __syncthreads();
        for (int idx = tid; idx < 8 * JT; idx += 256) {
            int ci = idx / JT, jj = idx % JT;
            int j = j_lo + jj;
            float v = (j >= 0 && j < NK) ? in[((size_t)b * 256 + ci0 + ci) * NK + j] : 0.f;
            s_in2[ci][jj] = pk2(v, v);
        }
        {
            const u64t* src = wz + (size_t)ci0 * 512;
            u64t* dst = &s_w[0][0][0];
            #pragma unroll
            for (int c = 0; c < 16; c++)
                dst[c * 256 + tid] = src[c * 256 + tid];
        }
        __syncthreads();
        #pragma unroll
        for (int ci = 0; ci < 8; ci++) {
            u64t w0[4], w1[4];
            #pragma unroll
            for (int i = 0; i < 4; i++) {
                w0[i] = s_w[ci][k0][ty + 16 * i];
                w1[i] = s_w[ci][k0 + 4][ty + 16 * i];
            }
            #pragma unroll
            for (int j = 0; j < 8; j++) {
                u64t i0 = s_in2[ci][jjb + 4 * j];
                u64t i1 = s_in2[ci][jjb + 4 * j - 1];
                #pragma unroll
                for (int i = 0; i < 4; i++) {
                    acc[i][j] = fma2(w0[i], i0, acc[i][j]);
                    acc[i][j] = fma2(w1[i], i1, acc[i][j]);
                }
            }
        }
    }
    #pragma unroll
    for (int i = 0; i < 4; i++) {
        int p = z * 64 + ty + 16 * i;
        int co0 = 2 * p, co1 = 2 * p + 1;
        float bv0 = bias[co0], bv1 = bias[co1];
        float* op0 = out + ((size_t)b * 256 + co0) * (size_t)NT;
        float* op1 = out + ((size_t)b * 256 + co1) * (size_t)NT;
        #pragma unroll
        for (int j = 0; j < 8; j++) {
            int t = ot0 + tx + 16 * j;
            float e0, e1;
            upk2(acc[i][j], e0, e1);
            op0[t] = __fadd_rn(e0, bv0);
            op1[t] = __fadd_rn(e1, bv1);
        }
    }
}

// ---------------- VQ dot GEMM: code-paired f32x2 ----------------
__global__ __launch_bounds__(256)
void vqdot2_k(const float* __restrict__ ze, const u64t* __restrict__ w2,
              float* __restrict__ dot)
{
    __shared__ u64t s_in2[16][64];
    __shared__ u64t s_w[16][128];

    const int b   = blockIdx.y;
    const int jt0 = blockIdx.x * 64;
    const int z   = blockIdx.z;
    const int tid = threadIdx.x;
    const int tx  = tid & 15;
    const int ty  = tid >> 4;

    u64t acc[8][4];
    #pragma unroll
    for (int i = 0; i < 8; i++)
        #pragma unroll
        for (int j = 0; j < 4; j++) acc[i][j] = 0ull;

    for (int ci0 = 0; ci0 < 128; ci0 += 16) {
        __syncthreads();
        for (int idx = tid; idx < 1024; idx += 256) {
            int ci = idx >> 6, t = idx & 63;
            float v = ze[((size_t)b * NCD + ci0 + ci) * NK + jt0 + t];
            s_in2[ci][t] = pk2(v, v);
        }
        for (int idx = tid; idx < 2048; idx += 256) {
            int ci = idx >> 7, p = idx & 127;
            s_w[ci][p] = w2[(size_t)(ci0 + ci) * 512 + z * 128 + p];
        }
        __syncthreads();
        #pragma unroll
        for (int ci = 0; ci < 16; ci++) {
            u64t xr[4], wv[8];
            #pragma unroll
            for (int j = 0; j < 4; j++) xr[j] = s_in2[ci][tx + 16 * j];
            #pragma unroll
            for (int i = 0; i < 8; i++) wv[i] = s_w[ci][ty + 16 * i];
            #pragma unroll
            for (int i = 0; i < 8; i++)
                #pragma unroll
                for (int j = 0; j < 4; j++)
                    acc[i][j] = fma2(wv[i], xr[j], acc[i][j]);
        }
    }
    #pragma unroll
    for (int i = 0; i < 8; i++) {
        int p = z * 128 + ty + 16 * i;
        float* o0 = dot + ((size_t)b * NCODES + 2 * p) * NK + jt0;
        float* o1 = dot + ((size_t)b * NCODES + 2 * p + 1) * NK + jt0;
        #pragma unroll
        for (int j = 0; j < 4; j++) {
            float e0, e1;
            upk2(acc[i][j], e0, e1);
            o0[tx + 16 * j] = e0;
            o1[tx + 16 * j] = e1;
        }
    }
}

// ---------------- generic direct conv ----------------
template<int KW, int STR, int PAD, int TTO, int COT, int TX, int RT, int RC, int CIC,
         bool INTR, bool OUTTR, bool GN>
__global__ __launch_bounds__(256)
void convk(const float* __restrict__ in, const float* __restrict__ w,
           const float* __restrict__ bias, float* __restrict__ out,
           const float* __restrict__ resid,
           const float* __restrict__ gmu, const float* __restrict__ grs,
           const float* __restrict__ gga, const float* __restrict__ gbe,
           int Cin, int Cout, int Tin, int Tout)
{
    constexpr int TY = 256 / TX;
    constexpr int IT = (TTO - 1) * STR + KW;
    static_assert(TX * RT == TTO, "t tiling");
    static_assert(TY * RC == COT, "c tiling");
    __shared__ float s_in[CIC][IT];
    __shared__ float s_w[CIC][KW][COT];

    const int b   = blockIdx.y;
    const int ot0 = blockIdx.x * TTO;
    const int co0 = blockIdx.z * COT;
    const int tid = threadIdx.x;
    const int tx  = tid % TX;
    const int ty  = tid / TX;

    float acc[RC][RT];
    #pragma unroll
    for (int i = 0; i < RC; i++)
        #pragma unroll
        for (int j = 0; j < RT; j++) acc[i][j] = 0.f;

    for (int ci0 = 0; ci0 < Cin; ci0 += CIC) {
        __syncthreads();
        for (int idx = tid; idx < CIC * IT; idx += 256) {
            int ci = idx / IT, t = idx % IT;
            int gci = ci0 + ci;
            int gt = ot0 * STR - PAD + t;
            float v = 0.f;
            if (gt >= 0 && gt < Tin) {
                v = INTR ? in[((size_t)b * Tin + gt) * Cin + gci]
                         : in[((size_t)b * Cin + gci) * (size_t)Tin + gt];
                if (GN) {
                    int gg = gci >> 5;
                    float y = (v - gmu[b * NG + gg]) * grs[b * NG + gg] * gga[gci] + gbe[gci];
                    v = silu(y);
                }
            }
            s_in[ci][t] = v;
        }
        for (int idx = tid; idx < CIC * KW * COT; idx += 256) {
            int ci = idx / (KW * COT);
            int r  = idx % (KW * COT);
            int kk = r / COT;
            int co = r % COT;
            s_w[ci][kk][co] = w[((size_t)(co0 + co) * Cin + ci0 + ci) * KW + kk];
        }
        __syncthreads();
        #pragma unroll 4
        for (int ci = 0; ci < CIC; ci++) {
            #pragma unroll
            for (int kk = 0; kk < KW; kk++) {
                float wr[RC], ir[RT];
                #pragma unroll
                for (int i = 0; i < RC; i++) wr[i] = s_w[ci][kk][ty + TY * i];
                #pragma unroll
                for (int j = 0; j < RT; j++) ir[j] = s_in[ci][(tx + TX * j) * STR + kk];
                #pragma unroll
                for (int i = 0; i < RC; i++)
                    #pragma unroll
                    for (int j = 0; j < RT; j++) acc[i][j] = fmaf(wr[i], ir[j], acc[i][j]);
            }
        }
    }
    #pragma unroll
    for (int i = 0; i < RC; i++) {
        int gco = co0 + ty + TY * i;
        float bv = bias ? bias[gco] : 0.f;
        #pragma unroll
        for (int j = 0; j < RT; j++) {
            int gt = ot0 + tx + TX * j;
            float v = __fadd_rn(acc[i][j], bv);
            if (resid) v = __fadd_rn(resid[((size_t)b * Cout + gco) * (size_t)Tout + gt], v);
            if (OUTTR) out[((size_t)b * Tout + gt) * Cout + gco] = v;
            else       out[((size_t)b * Cout + gco) * (size_t)Tout + gt] = v;
        }
    }
}

// ---------------- GroupNorm stats: ONE-pass (Σx, Σx²), 512 threads ----------------
// var = E[x²] − μ² (formula validated flip-safe in R13's gnfin path)
__global__ __launch_bounds__(512)
void gnstats_k(const float* __restrict__ act, float* __restrict__ mu, float* __restrict__ rs)
{
    int bg = blockIdx.x;
    const float4* p = reinterpret_cast<const float4*>(act + (size_t)bg * 65536);
    __shared__ float sha[16], shb[16];

    float s = 0.f, s2 = 0.f;
    for (int i = threadIdx.x; i < 16384; i += 512) {
        float4 v = p[i];
        s  += v.x + v.y + v.z + v.w;
        s2 += v.x * v.x + v.y * v.y + v.z * v.z + v.w * v.w;
    }
    #pragma unroll
    for (int o = 16; o; o >>= 1) {
        s  += __shfl_down_sync(0xffffffffu, s, o);
        s2 += __shfl_down_sync(0xffffffffu, s2, o);
    }
    if ((threadIdx.x & 31) == 0) {
        sha[threadIdx.x >> 5] = s;
        shb[threadIdx.x >> 5] = s2;
    }
    __syncthreads();
    if (threadIdx.x == 0) {
        float a = 0.f, c = 0.f;
        #pragma unroll
        for (int i = 0; i < 16; i++) { a += sha[i]; c += shb[i]; }
        float m = a * (1.f / 65536.f);
        float var = fmaxf(c * (1.f / 65536.f) - m * m, 0.f);
        mu[bg] = m;
        rs[bg] = rsqrtf(var + 1e-5f);
    }
}

// ---------------- VQ helpers ----------------
__global__ void init_k(float* counts, float* acc)
{
    int i = blockIdx.x * 256 + threadIdx.x;
    if (i < NCODES) counts[i] = 0.f;
    if (i < 4) acc[i] = 0.f;
}

__global__ void cb2_k(const float* __restrict__ cb, float* __restrict__ cb2)
{
    int n = blockIdx.x * 256 + threadIdx.x;
    if (n < NCODES) {
        float s = 0.f;
        for (int c = 0; c < NCD; c++) {
            float v = cb[n * NCD + c];
            s = __fadd_rn(s, __fmul_rn(v, v));
        }
        cb2[n] = s;
    }
}

__global__ __launch_bounds__(256)
void argmin_k(const float* __restrict__ dot, const float* __restrict__ cb2,
              const float* __restrict__ ze,
              int* __restrict__ codes, float* __restrict__ counts, float* __restrict__ out_codes)
{
    int idx = blockIdx.x * 256 + threadIdx.x;
    int b = idx >> 9, j = idx & 511;
    const float* zp = ze + ((size_t)b * NCD) * NK + j;
    float z2 = 0.f;
    for (int c = 0; c < NCD; c++) {
        float v = zp[(size_t)c * NK];
        z2 = __fadd_rn(z2, __fmul_rn(v, v));
    }
    const float* dp = dot + ((size_t)b * NCODES) * NK + j;
    float best = 3.4e38f;
    int bn = 0;
    for (int n = 0; n < NCODES; n++) {
        float t = __fadd_rn(z2, cb2[n]);
        float v = __fsub_rn(t, __fmul_rn(2.f, dp[(size_t)n * NK]));
        if (v < best) { best = v; bn = n; }
    }
    codes[idx] = bn;
    atomicAdd(&counts[bn], 1.f);
    out_codes[idx] = (float)bn;
}

__global__ __launch_bounds__(256)
void zq_k(const float* __restrict__ ze, const float* __restrict__ cb,
          const int* __restrict__ codes, float* __restrict__ zq_st, float* __restrict__ acc)
{
    int i = blockIdx.x * 256 + threadIdx.x;
    int j = i & 511;
    int c = (i >> 9) & 127;
    int b = i >> 16;
    int code = codes[(b << 9) | j];
    float q = cb[code * NCD + c];
    float z = ze[i];
    float d = __fsub_rn(q, z);
    zq_st[i] = __fadd_rn(z, d);
    float v = blockReduceSum256(d * d);
    if (threadIdx.x == 0) atomicAdd(&acc[0], v);
}

// ---------------- recon losses ----------------
__global__ __launch_bounds__(256)
void recon_k(const float* __restrict__ x, const float* __restrict__ mask,
             const float* __restrict__ xhat, float* __restrict__ acc)
{
    int idx = blockIdx.x * 256 + threadIdx.x;
    const float* xr = x + (size_t)idx * NIN;
    const float* hr = xhat + (size_t)idx * NIN;
    float ps = 0.f;
    #pragma unroll
    for (int d = 0; d < 24; d++) {
        int dd = (d < 21) ? d : d + 6;
        float df = hr[dd] - xr[dd];
        float ad = fabsf(df);
        ps += (ad < 1.f) ? 0.5f * df * df : ad - 0.5f;
    }
    float mL = mask[(size_t)idx * 2 + 0];
    float mR = mask[(size_t)idx * 2 + 1];
    float dn = 0.f, dd_ = 0.f;
    const int off[4] = {21, 24, 30, 33};
    #pragma unroll
    for (int v = 0; v < 4; v++) {
        int o = off[v];
        float x0 = xr[o], x1 = xr[o + 1], x2 = xr[o + 2];
        float h0 = hr[o], h1 = hr[o + 1], h2 = hr[o + 2];
        float nx = sqrtf(x0 * x0 + x1 * x1 + x2 * x2) + 1e-8f;
        float nh = sqrtf(h0 * h0 + h1 * h1 + h2 * h2) + 1e-8f;
        float cs = (x0 * h0 + x1 * h1 + x2 * h2) / (nx * nh);
        float m = (v < 2) ? mL : mR;
        dn += (1.f - cs) * m;
        dd_ += m;
    }
    float r0 = blockReduceSum256(ps);
    float r1 = blockReduceSum256(dn);
    float r2 = blockReduceSum256(dd_);
    if (threadIdx.x == 0) {
        atomicAdd(&acc[1], r0);
        atomicAdd(&acc[2], r1);
        atomicAdd(&acc[3], r2);
    }
}

__global__ __launch_bounds__(1024)
void finalize_k(const float* __restrict__ counts, const float* __restrict__ acc,
                float* __restrict__ out)
{
    __shared__ float sh[32];
    int t = threadIdx.x;
    float a = counts[t] * (1.f / (float)(NB * NK));
    float v = a * logf(a + 1e-10f);
    #pragma unroll
    for (int o = 16; o; o >>= 1) v += __shfl_down_sync(0xffffffffu, v, o);
    if ((t & 31) == 0) sh[t >> 5] = v;
    __syncthreads();
    if (t == 0) {
        float s = 0.f;
        #pragma unroll
        for (int i = 0; i < 32; i++) s += sh[i];
        out[0] = acc[0] * (1.25f / (float)(NB * NCD * NK));
        out[1] = expf(-s);
        out[2] = acc[1] * (1.f / (float)(NB * NT));
        out[3] = acc[2] / fmaxf(acc[3], 1.f);
    }
}

// ---------------- host orchestration ----------------
extern "C" void kernel_launch(void* const* d_in, const int* in_sizes, int n_in,
                              void* d_out, int out_size)
{
    const float* x          = (const float*)d_in[0];
    const float* mask       = (const float*)d_in[1];
    const float* enc_in_w   = (const float*)d_in[2];
    const float* enc_in_b   = (const float*)d_in[3];
    const float* enc_gn1_g  = (const float*)d_in[4];
    const float* enc_gn1_b  = (const float*)d_in[5];
    const float* enc_c1_w   = (const float*)d_in[6];
    const float* enc_c1_b   = (const float*)d_in[7];
    const float* enc_gn2_g  = (const float*)d_in[8];
    const float* enc_gn2_b  = (const float*)d_in[9];
    const float* enc_c2_w   = (const float*)d_in[10];
    const float* enc_c2_b   = (const float*)d_in[11];
    const float* down_w     = (const float*)d_in[12];
    const float* down_b     = (const float*)d_in[13];
    const float* enc_out_w  = (const float*)d_in[14];
    const float* enc_out_b  = (const float*)d_in[15];
    const float* codebook   = (const float*)d_in[16];
    const float* dec_in_w   = (const float*)d_in[17];
    const float* dec_in_b   = (const float*)d_in[18];
    const float* up_w       = (const float*)d_in[19];
    const float* up_b       = (const float*)d_in[20];
    const float* dec_gn1_g  = (const float*)d_in[21];
    const float* dec_gn1_b  = (const float*)d_in[22];
    const float* dec_c1_w   = (const float*)d_in[23];
    const float* dec_c1_b   = (const float*)d_in[24];
    const float* dec_gn2_g  = (const float*)d_in[25];
    const float* dec_gn2_b  = (const float*)d_in[26];
    const float* dec_c2_w   = (const float*)d_in[27];
    const float* dec_c2_b   = (const float*)d_in[28];
    const float* dec_out_w  = (const float*)d_in[29];
    const float* dec_out_b  = (const float*)d_in[30];

    float *bufA, *bufB, *bufC, *small, *ze, *zq, *mu, *rs, *cb2, *counts, *acc;
    int* codes;
    u64t *wT, *wdown, *wup, *wcb;
    cudaGetSymbolAddress((void**)&bufA, g_bufA);
    cudaGetSymbolAddress((void**)&bufB, g_bufB);
    cudaGetSymbolAddress((void**)&bufC, g_bufC);
    cudaGetSymbolAddress((void**)&small, g_small);
    cudaGetSymbolAddress((void**)&ze, g_ze);
    cudaGetSymbolAddress((void**)&zq, g_zq);
    cudaGetSymbolAddress((void**)&mu, g_mu);
    cudaGetSymbolAddress((void**)&rs, g_rs);
    cudaGetSymbolAddress((void**)&cb2, g_cb2);
    cudaGetSymbolAddress((void**)&counts, g_counts);
    cudaGetSymbolAddress((void**)&acc, g_acc);
    cudaGetSymbolAddress((void**)&codes, g_codes);
    cudaGetSymbolAddress((void**)&wT, g_wT);
    cudaGetSymbolAddress((void**)&wdown, g_wdown);
    cudaGetSymbolAddress((void**)&wup, g_wup);
    cudaGetSymbolAddress((void**)&wcb, g_wcb);

    cudaFuncSetAttribute(conv3k<true, false>,
                         cudaFuncAttributeMaxDynamicSharedMemorySize, C3_SMEM);
    cudaFuncSetAttribute(conv3k<true, true>,
                         cudaFuncAttributeMaxDynamicSharedMemorySize, C3_SMEM);

    float* out = (float*)d_out;
    float* out_xhat = out;
    float* out_codes = out + (size_t)NB * NT * NIN;
    float* out_scal = out_codes + (size_t)NB * NK;

    init_k<<<4, 256>>>(counts, acc);
    wprep_k<<<(16 * WT_PER_LAYER) / 256, 256>>>(enc_c1_w, enc_c2_w, dec_c1_w, dec_c2_w, wT);
    wprep_down<<<WDU_ELEMS / 256, 256>>>(down_w, wdown);
    wprep_up<<<WDU_ELEMS / 256, 256>>>(up_w, wup);
    cbprep_k<<<(NCD * (NCODES / 2)) / 256, 256>>>(codebook, wcb);

    // ---- encoder ----
    convk<3, 1, 1, 128, 128, 16, 8, 8, 12, true, false, false><<<dim3(16, NB, 2), 256>>>(
        x, enc_in_w, enc_in_b, bufA, nullptr, nullptr, nullptr, nullptr, nullptr,
        NIN, NH, NT, NT);

    float* cur = bufA;
    float* oth = bufC;
    for (int r = 0; r < NRES; r++) {
        gnstats_k<<<NB * NG, 512>>>(cur, mu, rs);
        conv3k<true, false><<<dim3(16, NB, 2), 256, C3_SMEM>>>(
            cur, wT + (size_t)r * WT_PER_LAYER, enc_c1_b + r * NH, bufB, nullptr,
            mu, rs, enc_gn1_g + r * NH, enc_gn1_b + r * NH);
        gnstats_k<<<NB * NG, 512>>>(bufB, mu, rs);
        conv3k<true, true><<<dim3(16, NB, 2), 256, C3_SMEM>>>(
            bufB, wT + (size_t)(4 + r) * WT_PER_LAYER, enc_c2_b + r * NH, oth, cur,
            mu, rs, enc_gn2_g + r * NH, enc_gn2_b + r * NH);
        float* t = cur; cur = oth; oth = t;
    }
    down_k<<<dim3(8, NB, 2), 256>>>(cur, wdown, down_b, small);
    convk<1, 1, 0, 128, 128, 16, 8, 8, 32, false, false, false><<<dim3(4, NB, 1), 256>>>(
        small, enc_out_w, enc_out_b, ze, nullptr, nullptr, nullptr, nullptr, nullptr,
        NH, NCD, NK, NK);

    // ---- VQ ----
    cb2_k<<<4, 256>>>(codebook, cb2);
    vqdot2_k<<<dim3(8, NB, 4), 256>>>(ze, wcb, bufC);
    argmin_k<<<(NB * NK) / 256, 256>>>(bufC, cb2, ze, codes, counts, out_codes);
    zq_k<<<(NB * NCD * NK) / 256, 256>>>(ze, codebook, codes, zq, acc);

    // ---- decoder ----
    convk<1, 1, 0, 128, 128, 16, 8, 8, 32, false, false, false><<<dim3(4, NB, 2), 256>>>(
        zq, dec_in_w, dec_in_b, small, nullptr, nullptr, nullptr, nullptr, nullptr,
        NCD, NH, NK, NK);
    up2_k<<<dim3(16, NB, 2), 256>>>(small, wup, up_b, bufA);

    cur = bufA;
    oth = bufC;
    for (int r = 0; r < NRES; r++) {
        gnstats_k<<<NB * NG, 512>>>(cur, mu, rs);
        conv3k<true, false><<<dim3(16, NB, 2), 256, C3_SMEM>>>(
            cur, wT + (size_t)(8 + r) * WT_PER_LAYER, dec_c1_b + r * NH, bufB, nullptr,
            mu, rs, dec_gn1_g + r * NH, dec_gn1_b + r * NH);
        gnstats_k<<<NB * NG, 512>>>(bufB, mu, rs);
        conv3k<true, true><<<dim3(16, NB, 2), 256, C3_SMEM>>>(
            bufB, wT + (size_t)(12 + r) * WT_PER_LAYER, dec_c2_b + r * NH, oth, cur,
            mu, rs, dec_gn2_g + r * NH, dec_gn2_b + r * NH);
        float* t = cur; cur = oth; oth = t;
    }
    convk<3, 1, 1, 128, 36, 64, 2, 9, 32, false, true, false><<<dim3(16, NB, 1), 256>>>(
        cur, dec_out_w, dec_out_b, out_xhat, nullptr, nullptr, nullptr, nullptr, nullptr,
        NH, NIN, NT, NT);

    // ---- losses ----
    recon_k<<<(NB * NT) / 256, 256>>>(x, mask, out_xhat, acc);
    finalize_k<<<1, 1024>>>(counts, acc, out_scal);
}

// round 16
// speedup vs baseline: 1.1029x; 1.0029x over previous
#include <cuda_runtime.h>
#include <cuda_pipeline.h>
#include <math.h>
#include <stdint.h>

// ---------------- problem constants ----------------
#define NB 32
#define NT 2048
#define NIN 36
#define NH 256          // HIDDEN
#define NCD 128         // CODE_DIM
#define NCODES 1024
#define NSTR 4
#define NK (NT / NSTR)  // 512
#define NG 8            // GN groups
#define NRES 4

typedef unsigned long long u64t;

// ---------------- scratch (static device globals; no allocation) ----------------
__device__ float g_bufA[NB * NH * NT];   // 64 MB
__device__ float g_bufB[NB * NH * NT];   // 64 MB
__device__ float g_bufC[NB * NH * NT];   // 64 MB (VQ dot buffer)
__device__ float g_small[NB * NH * NK];  // 16 MB
__device__ float g_ze[NB * NCD * NK];    // 8 MB
__device__ float g_zq[NB * NCD * NK];    // 8 MB (straight-through z_q_st)
__device__ int   g_codes[NB * NK];
__device__ float g_mu[NB * NG];
__device__ float g_rs[NB * NG];
__device__ float g_cb2[NCODES];
__device__ float g_counts[NCODES];
__device__ float g_acc[4];               // 0: vq sumsq, 1: pos sum, 2: dir num, 3: dir den
// pre-transposed, pre-duplicated res-block weights:
#define WT_PER_LAYER (2 * 32 * 8 * 3 * 128)   // 196608 u64
__device__ u64t g_wT[16 * WT_PER_LAYER];      // 25 MB
// co-paired weights for down conv & up conv-transpose: [z][ci 0..255][kk 0..7][p 0..63]
#define WDU_ELEMS (2 * 256 * 8 * 64)          // 262144 u64
__device__ u64t g_wdown[WDU_ELEMS];
__device__ u64t g_wup[WDU_ELEMS];
// code-paired codebook for VQ dot: [c 0..127][p 0..511]
__device__ u64t g_wcb[NCD * (NCODES / 2)];    // 512 KB
// co-paired weights: enc_in conv [z 0..1][blk 0..2][ci 0..11][kk 0..2][p 0..63]
#define WENC_ELEMS (2 * 3 * 12 * 3 * 64)      // 13824 u64
__device__ u64t g_wenc[WENC_ELEMS];
// co-paired 1x1 weights: [ci][p]
__device__ u64t g_w1a[256 * 64];              // enc_out: Cin=256, pairs=64
__device__ u64t g_w1b[128 * 128];             // dec_in:  Cin=128, pairs=128

// dynamic smem layout for conv3k (per buffer): s_in(4224) s_inB(4224) s_w2(24576)
#define C3_BUF 33024
#define C3_SMEM (2 * C3_BUF)

// ---------------- packed f32x2 helpers (sm_103a FFMA2) ----------------
__device__ __forceinline__ u64t pk2(float lo, float hi) {
    u64t r; asm("mov.b64 %0, {%1, %2};" : "=l"(r) : "f"(lo), "f"(hi)); return r;
}
__device__ __forceinline__ u64t fma2(u64t a, u64t b, u64t c) {
    u64t d; asm("fma.rn.f32x2 %0, %1, %2, %3;" : "=l"(d) : "l"(a), "l"(b), "l"(c)); return d;
}
__device__ __forceinline__ void upk2(u64t p, float& lo, float& hi) {
    asm("mov.b64 {%0, %1}, %2;" : "=f"(lo), "=f"(hi) : "l"(p));
}

// ---------------- helpers ----------------
__device__ __forceinline__ float blockReduceSum256(float v) {
    __shared__ float sh[8];
    __syncthreads();
    #pragma unroll
    for (int o = 16; o; o >>= 1) v += __shfl_down_sync(0xffffffffu, v, o);
    if ((threadIdx.x & 31) == 0) sh[threadIdx.x >> 5] = v;
    __syncthreads();
    float s = 0.f;
    if (threadIdx.x == 0) {
        #pragma unroll
        for (int i = 0; i < 8; i++) s += sh[i];
    }
    return s;  // valid on thread 0 only
}

__device__ __forceinline__ float silu(float y) {
    return y * (1.0f / (1.0f + expf(-y)));
}

// ---------------- weight pre-transpose: res-block convs (dup-u64) ----------------
__global__ __launch_bounds__(256)
void wprep_k(const float* __restrict__ c1e, const float* __restrict__ c2e,
             const float* __restrict__ c1d, const float* __restrict__ c2d,
             u64t* __restrict__ wT)
{
    size_t i = (size_t)blockIdx.x * 256 + threadIdx.x;
    int l    = (int)(i / WT_PER_LAYER);
    int rem  = (int)(i % WT_PER_LAYER);
    int co   = rem & 127;
    int rem2 = rem >> 7;
    int kk   = rem2 % 3;
    int rem3 = rem2 / 3;
    int ci   = rem3 & 7;
    int blk  = rem3 >> 3;
    int c0   = blk & 31;
    int cb   = blk >> 5;
    const float* base = (l < 4) ? c1e : (l < 8) ? c2e : (l < 12) ? c1d : c2d;
    const float* wl = base + (size_t)(l & 3) * (256 * 256 * 3);
    float v = wl[((size_t)(cb * 128 + co) * 256 + c0 * 8 + ci) * 3 + kk];
    ((float2*)wT)[i] = make_float2(v, v);
}

// ---------------- weight pre-pack: down conv, co-pairs ----------------
__global__ __launch_bounds__(256)
void wprep_down(const float* __restrict__ dw, u64t* __restrict__ w2)
{
    int i = blockIdx.x * 256 + threadIdx.x;
    int p  = i & 63;
    int kk = (i >> 6) & 7;
    int ci = (i >> 9) & 255;
    int z  = i >> 17;
    int co = z * 128 + 2 * p;
    float a = dw[((size_t)co * 256 + ci) * 8 + kk];
    float b = dw[((size_t)(co + 1) * 256 + ci) * 8 + kk];
    ((float2*)w2)[i] = make_float2(a, b);
}

// ---------------- weight pre-pack: up conv-transpose, co-pairs ----------------
__global__ __launch_bounds__(256)
void wprep_up(const float* __restrict__ uw, u64t* __restrict__ w2)
{
    int i = blockIdx.x * 256 + threadIdx.x;
    int p  = i & 63;
    int kk = (i >> 6) & 7;
    int ci = (i >> 9) & 255;
    int z  = i >> 17;
    int co = z * 128 + 2 * p;
    float a = uw[((size_t)ci * 256 + co) * 8 + kk];
    float b = uw[((size_t)ci * 256 + co + 1) * 8 + kk];
    ((float2*)w2)[i] = make_float2(a, b);
}

// ---------------- codebook pre-pack: code-pairs, [c][p] layout ----------------
__global__ __launch_bounds__(256)
void cbprep_k(const float* __restrict__ cb, u64t* __restrict__ w2)
{
    int i = blockIdx.x * 256 + threadIdx.x;   // < 128*512
    int p = i & 511;
    int c = i >> 9;
    float a = cb[(size_t)(2 * p) * NCD + c];
    float b = cb[(size_t)(2 * p + 1) * NCD + c];
    ((float2*)w2)[(size_t)c * 512 + p] = make_float2(a, b);
}

// ---------------- weight pre-pack: enc_in conv co-pairs ----------------
// layout: [z][blk][ci][kk][p];  w layout (256, 36, 3)
__global__ __launch_bounds__(256)
void wprep_enc(const float* __restrict__ w, u64t* __restrict__ w2)
{
    int i = blockIdx.x * 256 + threadIdx.x;
    if (i >= WENC_ELEMS) return;
    int p   = i & 63;
    int kk  = (i >> 6) % 3;
    int ci  = (i / 192) % 12;
    int blk = (i / 2304) % 3;
    int z   = i / 6912;
    int co  = z * 128 + 2 * p;
    int cig = blk * 12 + ci;
    float a = w[((size_t)co * 36 + cig) * 3 + kk];
    float b = w[((size_t)(co + 1) * 36 + cig) * 3 + kk];
    ((float2*)w2)[i] = make_float2(a, b);
}

// ---------------- weight pre-pack: 1x1 co-pairs ([ci][p]); w layout (Cout, Cin) ----------------
__global__ __launch_bounds__(256)
void wprep1x1(const float* __restrict__ w, u64t* __restrict__ w2, int Cin, int pairs)
{
    int i = blockIdx.x * 256 + threadIdx.x;
    if (i >= Cin * pairs) return;
    int p = i % pairs;
    int ci = i / pairs;
    float a = w[(size_t)(2 * p) * Cin + ci];
    float b = w[(size_t)(2 * p + 1) * Cin + ci];
    ((float2*)w2)[i] = make_float2(a, b);
}

// ---------------- specialized k=3 s=1 p=1 conv (R8/R12 config, frozen) ----------------
template<bool GN, bool RES>
__global__ __launch_bounds__(256)
void conv3k(const float* __restrict__ in, const u64t* __restrict__ wlayer,
            const float* __restrict__ bias, float* __restrict__ out,
            const float* __restrict__ resid,
            const float* __restrict__ gmu, const float* __restrict__ grs,
            const float* __restrict__ gga, const float* __restrict__ gbe)
{
    extern __shared__ char smraw[];

    const int b   = blockIdx.y;
    const int ot0 = blockIdx.x * 128;
    const int tid = threadIdx.x;
    const int tx  = tid & 15;
    const int ty  = tid >> 4;

    const u64t* wtile_base = wlayer + (size_t)blockIdx.z * (32 * 3072);
    const float* inb = in + (size_t)b * 256 * 2048;
    const int fci = tid >> 5;
    const int ftt = tid & 31;

    u64t acc[8][4];
    #pragma unroll
    for (int i = 0; i < 8; i++)
        #pragma unroll
        for (int j = 0; j < 4; j++) acc[i][j] = 0ull;

    float pv[5];

    auto issue_in = [&](int it) {
        int gci = it * 8 + fci;
        const float* ip = inb + (size_t)gci * 2048 + ot0 - 1;
        #pragma unroll
        for (int j = 0; j < 5; j++) {
            int t = ftt + 32 * j;
            int gt = ot0 - 1 + t;
            bool ok = (j < 4 || t < 130) && (gt >= 0) && (gt < 2048);
            pv[j] = ok ? ip[t] : 0.f;
        }
    };

    auto issue_w = [&](int it, int bufsel) {
        char* dst = smraw + bufsel * C3_BUF + 8448;
        const char* src = (const char*)(wtile_base + (size_t)it * 3072);
        #pragma unroll
        for (int c = 0; c < 6; c++)
            __pipeline_memcpy_async(dst + (c * 256 + tid) * 16,
                                    src + (c * 256 + tid) * 16, 16);
        __pipeline_commit();
    };

    auto store_in = [&](int it, int bufsel) {
        float* s_in  = (float*)(smraw + bufsel * C3_BUF);
        float* s_inB = s_in + 1056;
        int gci = it * 8 + fci;
        float m_ = 0.f, r_ = 0.f, ga_ = 0.f, be_ = 0.f;
        if (GN) {
            int gg = gci >> 5;
            m_ = gmu[b * NG + gg];
            r_ = grs[b * NG + gg];
            ga_ = gga[gci];
            be_ = gbe[gci];
        }
        #pragma unroll
        for (int j = 0; j < 5; j++) {
            int t = ftt + 32 * j;
            if (j < 4 || t < 130) {
                int gt = ot0 - 1 + t;
                float v = 0.f;
                if (gt >= 0 && gt < 2048) {
                    v = pv[j];
                    if (GN) {
                        float y = (v - m_) * r_ * ga_ + be_;
                        v = silu(y);
                    }
                }
                s_in[fci * 132 + t] = v;
                if (t >= 1) s_inB[fci * 132 + t - 1] = v;
            }
        }
    };

    issue_in(0);
    issue_w(0, 0);
    store_in(0, 0);
    __pipeline_wait_prior(0);
    __syncthreads();

    for (int it = 0; it < 32; it++) {
        const int cur = it & 1;
        if (it < 31) {
            issue_in(it + 1);
            issue_w(it + 1, cur ^ 1);
        }
        const float* s_in  = (const float*)(smraw + cur * C3_BUF);
        const float* s_inB = s_in + 1056;
        const u64t*  s_w2  = (const u64t*)(smraw + cur * C3_BUF + 8448);
        #pragma unroll
        for (int ci = 0; ci < 8; ci++) {
            u64t P[2][3], Q[2][2];
            #pragma unroll
            for (int g = 0; g < 2; g++) {
                int t0 = tx * 4 + 64 * g;
                P[g][0] = *(const u64t*)&s_in[ci * 132 + t0];
                P[g][1] = *(const u64t*)&s_in[ci * 132 + t0 + 2];
                P[g][2] = *(const u64t*)&s_in[ci * 132 + t0 + 4];
                Q[g][0] = *(const u64t*)&s_inB[ci * 132 + t0];
                Q[g][1] = *(const u64t*)&s_inB[ci * 132 + t0 + 2];
            }
            #pragma unroll
            for (int kk = 0; kk < 3; kk++) {
                u64t wv[8];
                #pragma unroll
                for (int i = 0; i < 8; i++) {
                    int co = ty * 4 + (i & 3) + ((i >> 2) << 6);
                    wv[i] = s_w2[ci * 384 + kk * 128 + co];
                }
                #pragma unroll
                for (int i = 0; i < 8; i++) {
                    #pragma unroll
                    for (int g = 0; g < 2; g++) {
                        u64t x0, x1;
                        if (kk == 0)      { x0 = P[g][0]; x1 = P[g][1]; }
                        else if (kk == 1) { x0 = Q[g][0]; x1 = Q[g][1]; }
                        else              { x0 = P[g][1]; x1 = P[g][2]; }
                        acc[i][g * 2 + 0] = fma2(wv[i], x0, acc[i][g * 2 + 0]);
                        acc[i][g * 2 + 1] = fma2(wv[i], x1, acc[i][g * 2 + 1]);
                    }
                }
            }
        }
        if (it < 31) {
            store_in(it + 1, cur ^ 1);
            __pipeline_wait_prior(0);
        }
        __syncthreads();
    }

    const int co0 = blockIdx.z * 128;
    #pragma unroll
    for (int i = 0; i < 8; i++) {
        int co = co0 + ty * 4 + (i & 3) + ((i >> 2) << 6);
        float bv = bias[co];
        float* op = out + ((size_t)b * 256 + co) * 2048;
        const float* rp = RES ? (resid + ((size_t)b * 256 + co) * 2048) : nullptr;
        #pragma unroll
        for (int g = 0; g < 2; g++) {
            int t0 = ot0 + tx * 4 + 64 * g;
            float e0, e1, e2, e3;
            upk2(acc[i][g * 2 + 0], e0, e1);
            upk2(acc[i][g * 2 + 1], e2, e3);
            e0 = __fadd_rn(e0, bv);
            e1 = __fadd_rn(e1, bv);
            e2 = __fadd_rn(e2, bv);
            e3 = __fadd_rn(e3, bv);
            if (RES) {
                float4 rv = *(const float4*)(rp + t0);
                e0 = __fadd_rn(rv.x, e0);
                e1 = __fadd_rn(rv.y, e1);
                e2 = __fadd_rn(rv.z, e2);
                e3 = __fadd_rn(rv.w, e3);
            }
            float4 ov; ov.x = e0; ov.y = e1; ov.z = e2; ov.w = e3;
            *(float4*)(op + t0) = ov;
        }
    }
}

// ---------------- enc_in conv (k=3,s=1,p=1, Cin=36), co-paired f32x2 ----------------
// chain per output co: blk asc (ci0=0,12,24), ci asc, kk inner — identical to convk<CIC=12>.
__global__ __launch_bounds__(256)
void enc2_k(const float* __restrict__ x, const u64t* __restrict__ w2,
            const float* __restrict__ bias, float* __restrict__ out)
{
    __shared__ u64t s_in2[12][136];
    __shared__ u64t s_w[12][3][64];

    const int b   = blockIdx.y;
    const int ot0 = blockIdx.x * 128;
    const int z   = blockIdx.z;
    const int tid = threadIdx.x;
    const int tx  = tid & 15;
    const int ty  = tid >> 4;

    const u64t* wz = w2 + (size_t)z * 6912;

    u64t acc[4][8];
    #pragma unroll
    for (int i = 0; i < 4; i++)
        #pragma unroll
        for (int j = 0; j < 8; j++) acc[i][j] = 0ull;

    for (int blk = 0; blk < 3; blk++) {
        __syncthreads();
        for (int idx = tid; idx < 12 * 130; idx += 256) {
            int ci = idx / 130, t = idx % 130;
            int gt = ot0 - 1 + t;
            float v = (gt >= 0 && gt < 2048)
                ? x[((size_t)b * 2048 + gt) * 36 + blk * 12 + ci] : 0.f;
            s_in2[ci][t] = pk2(v, v);
        }
        {
            const u64t* src = wz + (size_t)blk * 2304;
            u64t* dst = &s_w[0][0][0];
            for (int idx = tid; idx < 2304; idx += 256)
                dst[idx] = src[idx];
        }
        __syncthreads();
        #pragma unroll
        for (int ci = 0; ci < 12; ci++) {
            #pragma unroll
            for (int kk = 0; kk < 3; kk++) {
                u64t wv[4], xr[8];
                #pragma unroll
                for (int i = 0; i < 4; i++) wv[i] = s_w[ci][kk][ty + 16 * i];
                #pragma unroll
                for (int j = 0; j < 8; j++) xr[j] = s_in2[ci][tx + 16 * j + kk];
                #pragma unroll
                for (int i = 0; i < 4; i++)
                    #pragma unroll
                    for (int j = 0; j < 8; j++)
                        acc[i][j] = fma2(wv[i], xr[j], acc[i][j]);
            }
        }
    }
    #pragma unroll
    for (int i = 0; i < 4; i++) {
        int p = z * 64 + ty + 16 * i;
        int co0 = 2 * p, co1 = 2 * p + 1;
        float bv0 = bias[co0], bv1 = bias[co1];
        float* op0 = out + ((size_t)b * 256 + co0) * 2048;
        float* op1 = out + ((size_t)b * 256 + co1) * 2048;
        #pragma unroll
        for (int j = 0; j < 8; j++) {
            int t = ot0 + tx + 16 * j;
            float e0, e1;
            upk2(acc[i][j], e0, e1);
            op0[t] = __fadd_rn(e0, bv0);
            op1[t] = __fadd_rn(e1, bv1);
        }
    }
}

// ---------------- 1x1 conv, co-paired f32x2 (ci ascending; bit-identical to convk) ----------------
template<int CIN, int PB>
__global__ __launch_bounds__(256)
void gemm2_k(const float* __restrict__ in, const u64t* __restrict__ w2,
             const float* __restrict__ bias, float* __restrict__ out)
{
    __shared__ u64t s_in2[16][64];
    __shared__ u64t s_w[16][PB];

    const int b   = blockIdx.y;
    const int jt0 = blockIdx.x * 64;
    const int tid = threadIdx.x;
    const int tx  = tid & 15;
    const int ty  = tid >> 4;
    const int COUT = 2 * PB;

    u64t acc[PB / 16][4];
    #pragma unroll
    for (int i = 0; i < PB / 16; i++)
        #pragma unroll
        for (int j = 0; j < 4; j++) acc[i][j] = 0ull;

    for (int ci0 = 0; ci0 < CIN; ci0 += 16) {
        __syncthreads();
        for (int idx = tid; idx < 1024; idx += 256) {
            int ci = idx >> 6, t = idx & 63;
            float v = in[((size_t)b * CIN + ci0 + ci) * 512 + jt0 + t];
            s_in2[ci][t] = pk2(v, v);
        }
        for (int idx = tid; idx < 16 * PB; idx += 256) {
            int ci = idx / PB, p = idx % PB;
            s_w[ci][p] = w2[(size_t)(ci0 + ci) * PB + p];
        }
        __syncthreads();
        #pragma unroll
        for (int ci = 0; ci < 16; ci++) {
            u64t xr[4], wv[PB / 16];
            #pragma unroll
            for (int j = 0; j < 4; j++) xr[j] = s_in2[ci][tx + 16 * j];
            #pragma unroll
            for (int i = 0; i < PB / 16; i++) wv[i] = s_w[ci][ty + 16 * i];
            #pragma unroll
            for (int i = 0; i < PB / 16; i++)
                #pragma unroll
                for (int j = 0; j < 4; j++)
                    acc[i][j] = fma2(wv[i], xr[j], acc[i][j]);
        }
    }
    #pragma unroll
    for (int i = 0; i < PB / 16; i++) {
        int p = ty + 16 * i;
        int co0 = 2 * p, co1 = 2 * p + 1;
        float bv0 = bias[co0], bv1 = bias[co1];
        float* o0 = out + ((size_t)b * COUT + co0) * 512 + jt0;
        float* o1 = out + ((size_t)b * COUT + co1) * 512 + jt0;
        #pragma unroll
        for (int j = 0; j < 4; j++) {
            float e0, e1;
            upk2(acc[i][j], e0, e1);
            o0[tx + 16 * j] = __fadd_rn(e0, bv0);
            o1[tx + 16 * j] = __fadd_rn(e1, bv1);
        }
    }
}

// ---------------- down conv (k=8,s=4,p=2), co-paired f32x2 ----------------
__global__ __launch_bounds__(256)
void down_k(const float* __restrict__ in, const u64t* __restrict__ w2,
            const float* __restrict__ bias, float* __restrict__ out)
{
    __shared__ u64t s_in2[4][264];
    __shared__ u64t s_w[4][8][64];

    const int b   = blockIdx.y;
    const int ot0 = blockIdx.x * 64;
    const int z   = blockIdx.z;
    const int tid = threadIdx.x;
    const int tx  = tid & 15;
    const int ty  = tid >> 4;

    const float* inb = in + (size_t)b * 256 * 2048;
    const u64t* wz = w2 + (size_t)z * (256 * 8 * 64);

    u64t acc[4][4];
    #pragma unroll
    for (int i = 0; i < 4; i++)
        #pragma unroll
        for (int j = 0; j < 4; j++) acc[i][j] = 0ull;

    for (int ci0 = 0; ci0 < 256; ci0 += 4) {
        __syncthreads();
        for (int idx = tid; idx < 4 * 260; idx += 256) {
            int ci = idx / 260, t = idx % 260;
            int gt = ot0 * 4 - 2 + t;
            float v = (gt >= 0 && gt < 2048) ? inb[(size_t)(ci0 + ci) * 2048 + gt] : 0.f;
            s_in2[ci][t] = pk2(v, v);
        }
        {
            const u64t* src = wz + (size_t)ci0 * 512;
            u64t* dst = &s_w[0][0][0];
            #pragma unroll
            for (int c = 0; c < 8; c++)
                dst[c * 256 + tid] = src[c * 256 + tid];
        }
        __syncthreads();
        #pragma unroll
        for (int ci = 0; ci < 4; ci++) {
            #pragma unroll
            for (int kk = 0; kk < 8; kk++) {
                u64t xr[4], wv[4];
                #pragma unroll
                for (int j = 0; j < 4; j++) xr[j] = s_in2[ci][(tx + 16 * j) * 4 + kk];
                #pragma unroll
                for (int i = 0; i < 4; i++) wv[i] = s_w[ci][kk][ty + 16 * i];
                #pragma unroll
                for (int i = 0; i < 4; i++)
                    #pragma unroll
                    for (int j = 0; j < 4; j++)
                        acc[i][j] = fma2(wv[i], xr[j], acc[i][j]);
            }
        }
    }
    #pragma unroll
    for (int i = 0; i < 4; i++) {
        int p = z * 64 + ty + 16 * i;
        int co0 = 2 * p, co1 = 2 * p + 1;
        float bv0 = bias[co0], bv1 = bias[co1];
        float* op0 = out + ((size_t)b * 256 + co0) * 512;
        float* op1 = out + ((size_t)b * 256 + co1) * 512;
        #pragma unroll
        for (int j = 0; j < 4; j++) {
            int t = ot0 + tx + 16 * j;
            float e0, e1;
            upk2(acc[i][j], e0, e1);
            op0[t] = __fadd_rn(e0, bv0);
            op1[t] = __fadd_rn(e1, bv1);
        }
    }
}

// ---------------- up conv-transpose (k=8,s=4,p=2), co-paired f32x2 ----------------
__global__ __launch_bounds__(256)
void up2_k(const float* __restrict__ in, const u64t* __restrict__ w2,
           const float* __restrict__ bias, float* __restrict__ out)
{
    constexpr int JT = 36;
    __shared__ u64t s_in2[8][40];
    __shared__ u64t s_w[8][8][64];

    const int b = blockIdx.y, ot0 = blockIdx.x * 128, z = blockIdx.z;
    const int tid = threadIdx.x, tx = tid & 15, ty = tid >> 4;
    const int j_lo = (ot0 == 0) ? -2 : ((ot0 - 5) >> 2);
    const int tbase = ot0 + tx;
    const int k0 = (tbase + 2) & 3;
    const int jjb = ((tbase + 2 - k0) >> 2) - j_lo;

    const u64t* wz = w2 + (size_t)z * (256 * 8 * 64);

    u64t acc[4][8];
    #pragma unroll
    for (int i = 0; i < 4; i++)
        #pragma unroll
        for (int j = 0; j < 8; j++) acc[i][j] = 0ull;

    for (int ci0 = 0; ci0 < 256; ci0 += 8) {
        __syncthreads();
        for (int idx = tid; idx < 8 * JT; idx += 256) {
            int ci = idx / JT, jj = idx % JT;
            int j = j_lo + jj;
            float v = (j >= 0 && j < NK) ? in[((size_t)b * 256 + ci0 + ci) * NK + j] : 0.f;
            s_in2[ci][jj] = pk2(v, v);
        }
        {
            const u64t* src = wz + (size_t)ci0 * 512;
            u64t* dst = &s_w[0][0][0];
            #pragma unroll
            for (int c = 0; c < 16; c++)
                dst[c * 256 + tid] = src[c * 256 + tid];
        }
        __syncthreads();
        #pragma unroll
        for (int ci = 0; ci < 8; ci++) {
            u64t w0[4], w1[4];
            #pragma unroll
            for (int i = 0; i < 4; i++) {
                w0[i] = s_w[ci][k0][ty + 16 * i];
                w1[i] = s_w[ci][k0 + 4][ty + 16 * i];
            }
            #pragma unroll
            for (int j = 0; j < 8; j++) {
                u64t i0 = s_in2[ci][jjb + 4 * j];
                u64t i1 = s_in2[ci][jjb + 4 * j - 1];
                #pragma unroll
                for (int i = 0; i < 4; i++) {
                    acc[i][j] = fma2(w0[i], i0, acc[i][j]);
                    acc[i][j] = fma2(w1[i], i1, acc[i][j]);
                }
            }
        }
    }
    #pragma unroll
    for (int i = 0; i < 4; i++) {
        int p = z * 64 + ty + 16 * i;
        int co0 = 2 * p, co1 = 2 * p + 1;
        float bv0 = bias[co0], bv1 = bias[co1];
        float* op0 = out + ((size_t)b * 256 + co0) * (size_t)NT;
        float* op1 = out + ((size_t)b * 256 + co1) * (size_t)NT;
        #pragma unroll
        for (int j = 0; j < 8; j++) {
            int t = ot0 + tx + 16 * j;
            float e0, e1;
            upk2(acc[i][j], e0, e1);
            op0[t] = __fadd_rn(e0, bv0);
            op1[t] = __fadd_rn(e1, bv1);
        }
    }
}

// ---------------- VQ dot GEMM: code-paired f32x2, dense dot output (R14 path) ----------------
__global__ __launch_bounds__(256)
void vqdot2_k(const float* __restrict__ ze, const u64t* __restrict__ w2,
              float* __restrict__ dot)
{
    __shared__ u64t s_in2[16][64];
    __shared__ u64t s_w[16][128];

    const int b   = blockIdx.y;
    const int jt0 = blockIdx.x * 64;
    const int z   = blockIdx.z;
    const int tid = threadIdx.x;
    const int tx  = tid & 15;
    const int ty  = tid >> 4;

    u64t acc[8][4];
    #pragma unroll
    for (int i = 0; i < 8; i++)
        #pragma unroll
        for (int j = 0; j < 4; j++) acc[i][j] = 0ull;

    for (int ci0 = 0; ci0 < 128; ci0 += 16) {
        __syncthreads();
        for (int idx = tid; idx < 1024; idx += 256) {
            int ci = idx >> 6, t = idx & 63;
            float v = ze[((size_t)b * NCD + ci0 + ci) * NK + jt0 + t];
            s_in2[ci][t] = pk2(v, v);
        }
        for (int idx = tid; idx < 2048; idx += 256) {
            int ci = idx >> 7, p = idx & 127;
            s_w[ci][p] = w2[(size_t)(ci0 + ci) * 512 + z * 128 + p];
        }
        __syncthreads();
        #pragma unroll
        for (int ci = 0; ci < 16; ci++) {
            u64t xr[4], wv[8];
            #pragma unroll
            for (int j = 0; j < 4; j++) xr[j] = s_in2[ci][tx + 16 * j];
            #pragma unroll
            for (int i = 0; i < 8; i++) wv[i] = s_w[ci][ty + 16 * i];
            #pragma unroll
            for (int i = 0; i < 8; i++)
                #pragma unroll
                for (int j = 0; j < 4; j++)
                    acc[i][j] = fma2(wv[i], xr[j], acc[i][j]);
        }
    }
    #pragma unroll
    for (int i = 0; i < 8; i++) {
        int p = z * 128 + ty + 16 * i;
        float* o0 = dot + ((size_t)b * NCODES + 2 * p) * NK + jt0;
        float* o1 = dot + ((size_t)b * NCODES + 2 * p + 1) * NK + jt0;
        #pragma unroll
        for (int j = 0; j < 4; j++) {
            float e0, e1;
            upk2(acc[i][j], e0, e1);
            o0[tx + 16 * j] = e0;
            o1[tx + 16 * j] = e1;
        }
    }
}

// ---------------- generic direct conv (dec_out only) ----------------
template<int KW, int STR, int PAD, int TTO, int COT, int TX, int RT, int RC, int CIC,
         bool INTR, bool OUTTR, bool GN>
__global__ __launch_bounds__(256)
void convk(const float* __restrict__ in, const float* __restrict__ w,
           const float* __restrict__ bias, float* __restrict__ out,
           const float* __restrict__ resid,
           const float* __restrict__ gmu, const float* __restrict__ grs,
           const float* __restrict__ gga, const float* __restrict__ gbe,
           int Cin, int Cout, int Tin, int Tout)
{
    constexpr int TY = 256 / TX;
    constexpr int IT = (TTO - 1) * STR + KW;
    static_assert(TX * RT == TTO, "t tiling");
    static_assert(TY * RC == COT, "c tiling");
    __shared__ float s_in[CIC][IT];
    __shared__ float s_w[CIC][KW][COT];

    const int b   = blockIdx.y;
    const int ot0 = blockIdx.x * TTO;
    const int co0 = blockIdx.z * COT;
    const int tid = threadIdx.x;
    const int tx  = tid % TX;
    const int ty  = tid / TX;

    float acc[RC][RT];
    #pragma unroll
    for (int i = 0; i < RC; i++)
        #pragma unroll
        for (int j = 0; j < RT; j++) acc[i][j] = 0.f;

    for (int ci0 = 0; ci0 < Cin; ci0 += CIC) {
        __syncthreads();
        for (int idx = tid; idx < CIC * IT; idx += 256) {
            int ci = idx / IT, t = idx % IT;
            int gci = ci0 + ci;
            int gt = ot0 * STR - PAD + t;
            float v = 0.f;
            if (gt >= 0 && gt < Tin) {
                v = INTR ? in[((size_t)b * Tin + gt) * Cin + gci]
                         : in[((size_t)b * Cin + gci) * (size_t)Tin + gt];
                if (GN) {
                    int gg = gci >> 5;
                    float y = (v - gmu[b * NG + gg]) * grs[b * NG + gg] * gga[gci] + gbe[gci];
                    v = silu(y);
                }
            }
            s_in[ci][t] = v;
        }
        for (int idx = tid; idx < CIC * KW * COT; idx += 256) {
            int ci = idx / (KW * COT);
            int r  = idx % (KW * COT);
            int kk = r / COT;
            int co = r % COT;
            s_w[ci][kk][co] = w[((size_t)(co0 + co) * Cin + ci0 + ci) * KW + kk];
        }
        __syncthreads();
        #pragma unroll 4
        for (int ci = 0; ci < CIC; ci++) {
            #pragma unroll
            for (int kk = 0; kk < KW; kk++) {
                float wr[RC], ir[RT];
                #pragma unroll
                for (int i = 0; i < RC; i++) wr[i] = s_w[ci][kk][ty + TY * i];
                #pragma unroll
                for (int j = 0; j < RT; j++) ir[j] = s_in[ci][(tx + TX * j) * STR + kk];
                #pragma unroll
                for (int i = 0; i < RC; i++)
                    #pragma unroll
                    for (int j = 0; j < RT; j++) acc[i][j] = fmaf(wr[i], ir[j], acc[i][j]);
            }
        }
    }
    #pragma unroll
    for (int i = 0; i < RC; i++) {
        int gco = co0 + ty + TY * i;
        float bv = bias ? bias[gco] : 0.f;
        #pragma unroll
        for (int j = 0; j < RT; j++) {
            int gt = ot0 + tx + TX * j;
            float v = __fadd_rn(acc[i][j], bv);
            if (resid) v = __fadd_rn(resid[((size_t)b * Cout + gco) * (size_t)Tout + gt], v);
            if (OUTTR) out[((size_t)b * Tout + gt) * Cout + gco] = v;
            else       out[((size_t)b * Cout + gco) * (size_t)Tout + gt] = v;
        }
    }
}

// ---------------- GroupNorm stats: ONE-pass (Σx, Σx²), 512 threads ----------------
__global__ __launch_bounds__(512)
void gnstats_k(const float* __restrict__ act, float* __restrict__ mu, float* __restrict__ rs)
{
    int bg = blockIdx.x;
    const float4* p = reinterpret_cast<const float4*>(act + (size_t)bg * 65536);
    __shared__ float sha[16], shb[16];

    float s = 0.f, s2 = 0.f;
    for (int i = threadIdx.x; i < 16384; i += 512) {
        float4 v = p[i];
        s  += v.x + v.y + v.z + v.w;
        s2 += v.x * v.x + v.y * v.y + v.z * v.z + v.w * v.w;
    }
    #pragma unroll
    for (int o = 16; o; o >>= 1) {
        s  += __shfl_down_sync(0xffffffffu, s, o);
        s2 += __shfl_down_sync(0xffffffffu, s2, o);
    }
    if ((threadIdx.x & 31) == 0) {
        sha[threadIdx.x >> 5] = s;
        shb[threadIdx.x >> 5] = s2;
    }
    __syncthreads();
    if (threadIdx.x == 0) {
        float a = 0.f, c = 0.f;
        #pragma unroll
        for (int i = 0; i < 16; i++) { a += sha[i]; c += shb[i]; }
        float m = a * (1.f / 65536.f);
        float var = fmaxf(c * (1.f / 65536.f) - m * m, 0.f);
        mu[bg] = m;
        rs[bg] = rsqrtf(var + 1e-5f);
    }
}

// ---------------- VQ helpers ----------------
__global__ void init_k(float* counts, float* acc)
{
    int i = blockIdx.x * 256 + threadIdx.x;
    if (i < NCODES) counts[i] = 0.f;
    if (i < 4) acc[i] = 0.f;
}

__global__ void cb2_k(const float* __restrict__ cb, float* __restrict__ cb2)
{
    int n = blockIdx.x * 256 + threadIdx.x;
    if (n < NCODES) {
        float s = 0.f;
        for (int c = 0; c < NCD; c++) {
            float v = cb[n * NCD + c];
            s = __fadd_rn(s, __fmul_rn(v, v));
        }
        cb2[n] = s;
    }
}

// reference rounding sequence: dist = fl(fl(z2+cc) - fl(2*mm)); first-index tie-break
__global__ __launch_bounds__(256)
void argmin_k(const float* __restrict__ dot, const float* __restrict__ cb2,
              const float* __restrict__ ze,
              int* __restrict__ codes, float* __restrict__ counts, float* __restrict__ out_codes)
{
    int idx = blockIdx.x * 256 + threadIdx.x;
    int b = idx >> 9, j = idx & 511;
    const float* zp = ze + ((size_t)b * NCD) * NK + j;
    float z2 = 0.f;
    for (int c = 0; c < NCD; c++) {
        float v = zp[(size_t)c * NK];
        z2 = __fadd_rn(z2, __fmul_rn(v, v));
    }
    const float* dp = dot + ((size_t)b * NCODES) * NK + j;
    float best = 3.4e38f;
    int bn = 0;
    for (int n = 0; n < NCODES; n++) {
        float t = __fadd_rn(z2, cb2[n]);
        float v = __fsub_rn(t, __fmul_rn(2.f, dp[(size_t)n * NK]));
        if (v < best) { best = v; bn = n; }
    }
    codes[idx] = bn;
    atomicAdd(&counts[bn], 1.f);
    out_codes[idx] = (float)bn;
}

__global__ __launch_bounds__(256)
void zq_k(const float* __restrict__ ze, const float* __restrict__ cb,
          const int* __restrict__ codes, float* __restrict__ zq_st, float* __restrict__ acc)
{
    int i = blockIdx.x * 256 + threadIdx.x;
    int j = i & 511;
    int c = (i >> 9) & 127;
    int b = i >> 16;
    int code = codes[(b << 9) | j];
    float q = cb[code * NCD + c];
    float z = ze[i];
    float d = __fsub_rn(q, z);
    zq_st[i] = __fadd_rn(z, d);
    float v = blockReduceSum256(d * d);
    if (threadIdx.x == 0) atomicAdd(&acc[0], v);
}

// ---------------- recon losses ----------------
__global__ __launch_bounds__(256)
void recon_k(const float* __restrict__ x, const float* __restrict__ mask,
             const float* __restrict__ xhat, float* __restrict__ acc)
{
    int idx = blockIdx.x * 256 + threadIdx.x;
    const float* xr = x + (size_t)idx * NIN;
    const float* hr = xhat + (size_t)idx * NIN;
    float ps = 0.f;
    #pragma unroll
    for (int d = 0; d < 24; d++) {
        int dd = (d < 21) ? d : d + 6;
        float df = hr[dd] - xr[dd];
        float ad = fabsf(df);
        ps += (ad < 1.f) ? 0.5f * df * df : ad - 0.5f;
    }
    float mL = mask[(size_t)idx * 2 + 0];
    float mR = mask[(size_t)idx * 2 + 1];
    float dn = 0.f, dd_ = 0.f;
    const int off[4] = {21, 24, 30, 33};
    #pragma unroll
    for (int v = 0; v < 4; v++) {
        int o = off[v];
        float x0 = xr[o], x1 = xr[o + 1], x2 = xr[o + 2];
        float h0 = hr[o], h1 = hr[o + 1], h2 = hr[o + 2];
        float nx = sqrtf(x0 * x0 + x1 * x1 + x2 * x2) + 1e-8f;
        float nh = sqrtf(h0 * h0 + h1 * h1 + h2 * h2) + 1e-8f;
        float cs = (x0 * h0 + x1 * h1 + x2 * h2) / (nx * nh);
        float m = (v < 2) ? mL : mR;
        dn += (1.f - cs) * m;
        dd_ += m;
    }
    float r0 = blockReduceSum256(ps);
    float r1 = blockReduceSum256(dn);
    float r2 = blockReduceSum256(dd_);
    if (threadIdx.x == 0) {
        atomicAdd(&acc[1], r0);
        atomicAdd(&acc[2], r1);
        atomicAdd(&acc[3], r2);
    }
}

__global__ __launch_bounds__(1024)
void finalize_k(const float* __restrict__ counts, const float* __restrict__ acc,
                float* __restrict__ out)
{
    __shared__ float sh[32];
    int t = threadIdx.x;
    float a = counts[t] * (1.f / (float)(NB * NK));
    float v = a * logf(a + 1e-10f);
    #pragma unroll
    for (int o = 16; o; o >>= 1) v += __shfl_down_sync(0xffffffffu, v, o);
    if ((t & 31) == 0) sh[t >> 5] = v;
    __syncthreads();
    if (t == 0) {
        float s = 0.f;
        #pragma unroll
        for (int i = 0; i < 32; i++) s += sh[i];
        out[0] = acc[0] * (1.25f / (float)(NB * NCD * NK));
        out[1] = expf(-s);
        out[2] = acc[1] * (1.f / (float)(NB * NT));
        out[3] = acc[2] / fmaxf(acc[3], 1.f);
    }
}

// ---------------- host orchestration ----------------
extern "C" void kernel_launch(void* const* d_in, const int* in_sizes, int n_in,
                              void* d_out, int out_size)
{
    const float* x          = (const float*)d_in[0];
    const float* mask       = (const float*)d_in[1];
    const float* enc_in_w   = (const float*)d_in[2];
    const float* enc_in_b   = (const float*)d_in[3];
    const float* enc_gn1_g  = (const float*)d_in[4];
    const float* enc_gn1_b  = (const float*)d_in[5];
    const float* enc_c1_w   = (const float*)d_in[6];
    const float* enc_c1_b   = (const float*)d_in[7];
    const float* enc_gn2_g  = (const float*)d_in[8];
    const float* enc_gn2_b  = (const float*)d_in[9];
    const float* enc_c2_w   = (const float*)d_in[10];
    const float* enc_c2_b   = (const float*)d_in[11];
    const float* down_w     = (const float*)d_in[12];
    const float* down_b     = (const float*)d_in[13];
    const float* enc_out_w  = (const float*)d_in[14];
    const float* enc_out_b  = (const float*)d_in[15];
    const float* codebook   = (const float*)d_in[16];
    const float* dec_in_w   = (const float*)d_in[17];
    const float* dec_in_b   = (const float*)d_in[18];
    const float* up_w       = (const float*)d_in[19];
    const float* up_b       = (const float*)d_in[20];
    const float* dec_gn1_g  = (const float*)d_in[21];
    const float* dec_gn1_b  = (const float*)d_in[22];
    const float* dec_c1_w   = (const float*)d_in[23];
    const float* dec_c1_b   = (const float*)d_in[24];
    const float* dec_gn2_g  = (const float*)d_in[25];
    const float* dec_gn2_b  = (const float*)d_in[26];
    const float* dec_c2_w   = (const float*)d_in[27];
    const float* dec_c2_b   = (const float*)d_in[28];
    const float* dec_out_w  = (const float*)d_in[29];
    const float* dec_out_b  = (const float*)d_in[30];

    float *bufA, *bufB, *bufC, *small, *ze, *zq, *mu, *rs, *cb2, *counts, *acc;
    int* codes;
    u64t *wT, *wdown, *wup, *wcb, *wenc, *w1a, *w1b;
    cudaGetSymbolAddress((void**)&bufA, g_bufA);
    cudaGetSymbolAddress((void**)&bufB, g_bufB);
    cudaGetSymbolAddress((void**)&bufC, g_bufC);
    cudaGetSymbolAddress((void**)&small, g_small);
    cudaGetSymbolAddress((void**)&ze, g_ze);
    cudaGetSymbolAddress((void**)&zq, g_zq);
    cudaGetSymbolAddress((void**)&mu, g_mu);
    cudaGetSymbolAddress((void**)&rs, g_rs);
    cudaGetSymbolAddress((void**)&cb2, g_cb2);
    cudaGetSymbolAddress((void**)&counts, g_counts);
    cudaGetSymbolAddress((void**)&acc, g_acc);
    cudaGetSymbolAddress((void**)&codes, g_codes);
    cudaGetSymbolAddress((void**)&wT, g_wT);
    cudaGetSymbolAddress((void**)&wdown, g_wdown);
    cudaGetSymbolAddress((void**)&wup, g_wup);
    cudaGetSymbolAddress((void**)&wcb, g_wcb);
    cudaGetSymbolAddress((void**)&wenc, g_wenc);
    cudaGetSymbolAddress((void**)&w1a, g_w1a);
    cudaGetSymbolAddress((void**)&w1b, g_w1b);

    cudaFuncSetAttribute(conv3k<true, false>,
                         cudaFuncAttributeMaxDynamicSharedMemorySize, C3_SMEM);
    cudaFuncSetAttribute(conv3k<true, true>,
                         cudaFuncAttributeMaxDynamicSharedMemorySize, C3_SMEM);

    float* out = (float*)d_out;
    float* out_xhat = out;
    float* out_codes = out + (size_t)NB * NT * NIN;
    float* out_scal = out_codes + (size_t)NB * NK;

    init_k<<<4, 256>>>(counts, acc);
    wprep_k<<<(16 * WT_PER_LAYER) / 256, 256>>>(enc_c1_w, enc_c2_w, dec_c1_w, dec_c2_w, wT);
    wprep_down<<<WDU_ELEMS / 256, 256>>>(down_w, wdown);
    wprep_up<<<WDU_ELEMS / 256, 256>>>(up_w, wup);
    cbprep_k<<<(NCD * (NCODES / 2)) / 256, 256>>>(codebook, wcb);
    wprep_enc<<<(WENC_ELEMS + 255) / 256, 256>>>(enc_in_w, wenc);
    wprep1x1<<<64, 256>>>(enc_out_w, w1a, 256, 64);
    wprep1x1<<<64, 256>>>(dec_in_w, w1b, 128, 128);

    // ---- encoder ----
    enc2_k<<<dim3(16, NB, 2), 256>>>(x, wenc, enc_in_b, bufA);

    float* cur = bufA;
    float* oth = bufC;
    for (int r = 0; r < NRES; r++) {
        gnstats_k<<<NB * NG, 512>>>(cur, mu, rs);
        conv3k<true, false><<<dim3(16, NB, 2), 256, C3_SMEM>>>(
            cur, wT + (size_t)r * WT_PER_LAYER, enc_c1_b + r * NH, bufB, nullptr,
            mu, rs, enc_gn1_g + r * NH, enc_gn1_b + r * NH);
        gnstats_k<<<NB * NG, 512>>>(bufB, mu, rs);
        conv3k<true, true><<<dim3(16, NB, 2), 256, C3_SMEM>>>(
            bufB, wT + (size_t)(4 + r) * WT_PER_LAYER, enc_c2_b + r * NH, oth, cur,
            mu, rs, enc_gn2_g + r * NH, enc_gn2_b + r * NH);
        float* t = cur; cur = oth; oth = t;
    }
    down_k<<<dim3(8, NB, 2), 256>>>(cur, wdown, down_b, small);
    gemm2_k<256, 64><<<dim3(8, NB, 1), 256>>>(small, w1a, enc_out_b, ze);

    // ---- VQ (R14 path: dense dot into bufC, argmin with reference z2 rounding) ----
    cb2_k<<<4, 256>>>(codebook, cb2);
    vqdot2_k<<<dim3(8, NB, 4), 256>>>(ze, wcb, bufC);
    argmin_k<<<(NB * NK) / 256, 256>>>(bufC, cb2, ze, codes, counts, out_codes);
    zq_k<<<(NB * NCD * NK) / 256, 256>>>(ze, codebook, codes, zq, acc);

    // ---- decoder ----
    gemm2_k<128, 128><<<dim3(8, NB, 1), 256>>>(zq, w1b, dec_in_b, small);
    up2_k<<<dim3(16, NB, 2), 256>>>(small, wup, up_b, bufA);

    cur = bufA;
    oth = bufC;
    for (int r = 0; r < NRES; r++) {
        gnstats_k<<<NB * NG, 512>>>(cur, mu, rs);
        conv3k<true, false><<<dim3(16, NB, 2), 256, C3_SMEM>>>(
            cur, wT + (size_t)(8 + r) * WT_PER_LAYER, dec_c1_b + r * NH, bufB, nullptr,
            mu, rs, dec_gn1_g + r * NH, dec_gn1_b + r * NH);
        gnstats_k<<<NB * NG, 512>>>(bufB, mu, rs);
        conv3k<true, true><<<dim3(16, NB, 2), 256, C3_SMEM>>>(
            bufB, wT + (size_t)(12 + r) * WT_PER_LAYER, dec_c2_b + r * NH, oth, cur,
            mu, rs, dec_gn2_g + r * NH, dec_gn2_b + r * NH);
        float* t = cur; cur = oth; oth = t;
    }
    convk<3, 1, 1, 128, 36, 64, 2, 9, 32, false, true, false><<<dim3(16, NB, 1), 256>>>(
        cur, dec_out_w, dec_out_b, out_xhat, nullptr, nullptr, nullptr, nullptr, nullptr,
        NH, NIN, NT, NT);

    // ---- losses ----
    recon_k<<<(NB * NT) / 256, 256>>>(x, mask, out_xhat, acc);
    finalize_k<<<1, 1024>>>(counts, acc, out_scal);
}